// round 3
// baseline (speedup 1.0000x reference)
#include <cuda_runtime.h>

#define NMAX 50176
#define LN_EPS 1e-5f

__device__ float g_q[NMAX * 64];
__device__ float g_k[NMAX * 64];
__device__ float g_v[NMAX * 64];

typedef unsigned long long u64;

__device__ __forceinline__ u64 pack2(float x) {
    u64 r; asm("mov.b64 %0, {%1, %1};" : "=l"(r) : "f"(x)); return r;
}
__device__ __forceinline__ float2 unpk(u64 v) {
    float2 f; asm("mov.b64 {%0, %1}, %2;" : "=f"(f.x), "=f"(f.y) : "l"(v));
    return f;
}
__device__ __forceinline__ void fma2(u64& d, u64 a, u64 b) {
    asm("fma.rn.f32x2 %0, %1, %2, %0;" : "+l"(d) : "l"(a), "l"(b));
}
__device__ __forceinline__ void reduce8(float& a, float& b) {
#pragma unroll
    for (int off = 4; off > 0; off >>= 1) {
        a += __shfl_xor_sync(0xffffffffu, a, off);
        b += __shfl_xor_sync(0xffffffffu, b, off);
    }
}

// row stride for SMEM A-tiles: 68 floats -> 16B aligned, 2-way max conflict
#define RS 68

// ---------------------------------------------------------------------------
// Kernel A: q/k/v = feat @ W + b. 256 threads, 128 rows/block, 3 passes.
// Tile 4 rows x 8 cols per thread, packed f32x2 FMA.
// ---------------------------------------------------------------------------
__global__ __launch_bounds__(256, 2) void qkv_kernel(
    const float* __restrict__ feat, int N,
    const float* __restrict__ wq, const float* __restrict__ bq,
    const float* __restrict__ wk, const float* __restrict__ bk,
    const float* __restrict__ wv, const float* __restrict__ bv)
{
    extern __shared__ float sm[];
    float* swq = sm;              // 4096
    float* swk = swq + 4096;      // 4096
    float* swv = swk + 4096;      // 4096
    float* sb  = swv + 4096;      // 192
    float* sf  = sb + 192;        // 128 x RS

    const int t = threadIdx.x;
    for (int j = t; j < 4096; j += 256) {
        swq[j] = wq[j]; swk[j] = wk[j]; swv[j] = wv[j];
    }
    if (t < 64) { sb[t] = bq[t]; sb[64 + t] = bk[t]; sb[128 + t] = bv[t]; }

    const int row0 = blockIdx.x * 128;
    for (int j = t; j < 2048; j += 256) {
        const int row = j >> 4, c4 = (j & 15) << 2;
        float4 f4 = make_float4(0.f, 0.f, 0.f, 0.f);
        if (row0 + row < N) f4 = *(const float4*)(feat + (row0 + row) * 64 + c4);
        *(float4*)(sf + row * RS + c4) = f4;
    }
    __syncthreads();

    const int rg = t >> 3;          // 0..31: rows rg*4..rg*4+3
    const int c0 = (t & 7) << 3;    // cols c0..c0+7
    const float* fr = sf + rg * 4 * RS;

    const float* Ws[3] = { swq, swk, swv };
    float*       Gs[3] = { g_q, g_k, g_v };

#pragma unroll 1
    for (int m = 0; m < 3; m++) {
        const float* W = Ws[m];
        u64 acc[4][4];
        {
            const ulonglong2 b01 = *(const ulonglong2*)(sb + m * 64 + c0);
            const ulonglong2 b23 = *(const ulonglong2*)(sb + m * 64 + c0 + 4);
#pragma unroll
            for (int jj = 0; jj < 4; jj++) {
                acc[jj][0] = b01.x; acc[jj][1] = b01.y;
                acc[jj][2] = b23.x; acc[jj][3] = b23.y;
            }
        }
#pragma unroll 4
        for (int i4 = 0; i4 < 16; i4++) {
            float a0[4], a1[4], a2[4], a3[4];
            *(float4*)a0 = *(const float4*)(fr + 0 * RS + i4 * 4);
            *(float4*)a1 = *(const float4*)(fr + 1 * RS + i4 * 4);
            *(float4*)a2 = *(const float4*)(fr + 2 * RS + i4 * 4);
            *(float4*)a3 = *(const float4*)(fr + 3 * RS + i4 * 4);
#pragma unroll
            for (int j = 0; j < 4; j++) {
                const ulonglong2 w01 =
                    *(const ulonglong2*)(W + (i4 * 4 + j) * 64 + c0);
                const ulonglong2 w23 =
                    *(const ulonglong2*)(W + (i4 * 4 + j) * 64 + c0 + 4);
                u64 d;
                d = pack2(a0[j]);
                fma2(acc[0][0], d, w01.x); fma2(acc[0][1], d, w01.y);
                fma2(acc[0][2], d, w23.x); fma2(acc[0][3], d, w23.y);
                d = pack2(a1[j]);
                fma2(acc[1][0], d, w01.x); fma2(acc[1][1], d, w01.y);
                fma2(acc[1][2], d, w23.x); fma2(acc[1][3], d, w23.y);
                d = pack2(a2[j]);
                fma2(acc[2][0], d, w01.x); fma2(acc[2][1], d, w01.y);
                fma2(acc[2][2], d, w23.x); fma2(acc[2][3], d, w23.y);
                d = pack2(a3[j]);
                fma2(acc[3][0], d, w01.x); fma2(acc[3][1], d, w01.y);
                fma2(acc[3][2], d, w23.x); fma2(acc[3][3], d, w23.y);
            }
        }
        float* G = Gs[m];
#pragma unroll
        for (int jj = 0; jj < 4; jj++) {
            const int row = row0 + rg * 4 + jj;
            if (row < N) {
                ulonglong2 s0; s0.x = acc[jj][0]; s0.y = acc[jj][1];
                ulonglong2 s1; s1.x = acc[jj][2]; s1.y = acc[jj][3];
                *(ulonglong2*)(G + row * 64 + c0)     = s0;
                *(ulonglong2*)(G + row * 64 + c0 + 4) = s1;
            }
        }
    }
}

// ---------------------------------------------------------------------------
// Kernel B: fused point transformer. 256 threads = 8 warps, 1 point per warp,
// 2 passes => 16 points/block. GEMMs: tile 4x8, packed f32x2 FMA.
// All per-point phases are warp-local (syncwarp only).
// ---------------------------------------------------------------------------
__global__ __launch_bounds__(256, 2) void pt_kernel(
    const float* __restrict__ points, const float* __restrict__ feat,
    const int* __restrict__ nbr, int N,
    const float* __restrict__ wp,  const float* __restrict__ wg1,
    const float* __restrict__ wg2, const float* __restrict__ wo,
    const float* __restrict__ bp,  const float* __restrict__ gp,
    const float* __restrict__ betap,
    const float* __restrict__ bg1, const float* __restrict__ gg,
    const float* __restrict__ betag,
    const float* __restrict__ bg2, const float* __restrict__ bo,
    float* __restrict__ out)
{
    extern __shared__ float sm[];
    float* swg1  = sm;               // 4096
    float* swg2  = swg1 + 4096;      // 4096
    float* swp   = swg2 + 4096;      // 192
    float* sbias = swp  + 192;       // 512: bp|gp|betap|bg1|gg|betag|bg2|bo
    float* sM    = sbias + 512;      // 32
    float* sbf   = sM    + 32;       // 8 x 16 x RS
    float* sgvp  = sbf   + 8 * 16 * RS;
    float* smout = sgvp  + 8 * 16 * RS;  // 16 x 64

    const int t = threadIdx.x;
    for (int j = t; j < 4096; j += 256) { swg1[j] = wg1[j]; swg2[j] = wg2[j]; }
    for (int j = t; j < 192; j += 256) swp[j] = wp[j];
    if (t < 64) {
        sbias[t]       = bp[t];
        sbias[64 + t]  = gp[t];
        sbias[128 + t] = betap[t];
        sbias[192 + t] = bg1[t];
        sbias[256 + t] = gg[t];
        sbias[320 + t] = betag[t];
        sbias[384 + t] = bg2[t];
        sbias[448 + t] = bo[t];
    }
    __syncthreads();

    if (t < 20) {   // Gram matrix of [wp0,wp1,wp2,bp] for analytic pos-LN
        if (t < 16) {
            const int a = t >> 2, b = t & 3;
            const float* ra = (a < 3) ? (swp + a * 64) : sbias;
            const float* rb = (b < 3) ? (swp + b * 64) : sbias;
            float s = 0.f;
            for (int c = 0; c < 64; c++) s += ra[c] * rb[c];
            sM[t] = s;
        } else {
            const int a = t - 16;
            const float* ra = (a < 3) ? (swp + a * 64) : sbias;
            float s = 0.f;
            for (int c = 0; c < 64; c++) s += ra[c];
            sM[t] = s;
        }
    }
    __syncthreads();

    const int w = t >> 5;           // warp = point slot
    const int u = t & 31;

    float* mbf  = sbf  + w * 16 * RS;
    float* mgvp = sgvp + w * 16 * RS;

    // gather mapping: 2 row-groups of 8 x 16 col-groups of 4
    const int grg = u >> 4;             // rows grg*8..+7
    const int gc0 = (u & 15) << 2;      // cols gc0..gc0+3
    // GEMM mapping: 4 row-groups of 4 x 8 col-groups of 8
    const int rg2 = u >> 3;             // rows rg2*4..+3
    const int c0  = (u & 7) << 3;       // cols c0..c0+7

    // hoisted positional weights (gather mapping)
    const float4 wpx = *(const float4*)(swp + gc0);
    const float4 wpy = *(const float4*)(swp + 64 + gc0);
    const float4 wpz = *(const float4*)(swp + 128 + gc0);
    const float4 bp4 = *(const float4*)(sbias + gc0);
    const float4 gp4 = *(const float4*)(sbias + 64 + gc0);
    const float4 bt4 = *(const float4*)(sbias + 128 + gc0);

#pragma unroll 1
    for (int pass = 0; pass < 2; pass++) {
        const int n = blockIdx.x * 16 + pass * 8 + w;
        const int nn = (n < N) ? n : 0;

        // ---- gather + positional LN/relu (analytic stats) + attn_in ----
        {
            const float4 q4 = *(const float4*)(g_q + nn * 64 + gc0);
            const float ptx = points[nn * 3 + 0];
            const float pty = points[nn * 3 + 1];
            const float ptz = points[nn * 3 + 2];
            const int4 id0 = *(const int4*)(nbr + nn * 16 + grg * 8);
            const int4 id1 = *(const int4*)(nbr + nn * 16 + grg * 8 + 4);
            int ids[8] = { id0.x, id0.y, id0.z, id0.w,
                           id1.x, id1.y, id1.z, id1.w };
#pragma unroll
            for (int jj = 0; jj < 8; jj++) {
                const int r = grg * 8 + jj;
                const int id = ids[jj];
                const float rx = points[id * 3 + 0] - ptx;
                const float ry = points[id * 3 + 1] - pty;
                const float rz = points[id * 3 + 2] - ptz;

                const float s1 = fmaf(rx, sM[16], fmaf(ry, sM[17],
                                 fmaf(rz, sM[18], sM[19])));
                const float tx = fmaf(rx, sM[0],  fmaf(ry, sM[1],
                                 fmaf(rz, sM[2],  sM[3])));
                const float ty = fmaf(rx, sM[4],  fmaf(ry, sM[5],
                                 fmaf(rz, sM[6],  sM[7])));
                const float tz = fmaf(rx, sM[8],  fmaf(ry, sM[9],
                                 fmaf(rz, sM[10], sM[11])));
                const float tw = fmaf(rx, sM[12], fmaf(ry, sM[13],
                                 fmaf(rz, sM[14], sM[15])));
                const float s2 = fmaf(rx, tx, fmaf(ry, ty, fmaf(rz, tz, tw)));
                const float mean = s1 * 0.015625f;
                const float var  = s2 * 0.015625f - mean * mean;
                const float inv  = rsqrtf(var + LN_EPS);

                float pr[4], pv[4];
                pr[0] = fmaf(rx, wpx.x, fmaf(ry, wpy.x, fmaf(rz, wpz.x, bp4.x)));
                pr[1] = fmaf(rx, wpx.y, fmaf(ry, wpy.y, fmaf(rz, wpz.y, bp4.y)));
                pr[2] = fmaf(rx, wpx.z, fmaf(ry, wpy.z, fmaf(rz, wpz.z, bp4.z)));
                pr[3] = fmaf(rx, wpx.w, fmaf(ry, wpy.w, fmaf(rz, wpz.w, bp4.w)));
                pv[0] = fmaxf(fmaf((pr[0] - mean) * inv, gp4.x, bt4.x), 0.f);
                pv[1] = fmaxf(fmaf((pr[1] - mean) * inv, gp4.y, bt4.y), 0.f);
                pv[2] = fmaxf(fmaf((pr[2] - mean) * inv, gp4.z, bt4.z), 0.f);
                pv[3] = fmaxf(fmaf((pr[3] - mean) * inv, gp4.w, bt4.w), 0.f);

                const float4 gk4 = *(const float4*)(g_k + id * 64 + gc0);
                const float4 gv4 = *(const float4*)(g_v + id * 64 + gc0);

                *(float4*)(mbf + r * RS + gc0) =
                    make_float4(q4.x - gk4.x + pv[0], q4.y - gk4.y + pv[1],
                                q4.z - gk4.z + pv[2], q4.w - gk4.w + pv[3]);
                *(float4*)(mgvp + r * RS + gc0) =
                    make_float4(gv4.x + pv[0], gv4.y + pv[1],
                                gv4.z + pv[2], gv4.w + pv[3]);
            }
        }
        __syncwarp();

        const float* mrow = mbf + rg2 * 4 * RS;

        // ---- GEMM1: h = relu(LN(attn_in @ wg1 + bg1)), packed f32x2 ----
        {
            u64 acc[4][4];
            {
                const ulonglong2 b01 = *(const ulonglong2*)(sbias + 192 + c0);
                const ulonglong2 b23 = *(const ulonglong2*)(sbias + 192 + c0 + 4);
#pragma unroll
                for (int jj = 0; jj < 4; jj++) {
                    acc[jj][0] = b01.x; acc[jj][1] = b01.y;
                    acc[jj][2] = b23.x; acc[jj][3] = b23.y;
                }
            }
#pragma unroll 4
            for (int i4 = 0; i4 < 16; i4++) {
                float a0[4], a1[4], a2[4], a3[4];
                *(float4*)a0 = *(const float4*)(mrow + 0 * RS + i4 * 4);
                *(float4*)a1 = *(const float4*)(mrow + 1 * RS + i4 * 4);
                *(float4*)a2 = *(const float4*)(mrow + 2 * RS + i4 * 4);
                *(float4*)a3 = *(const float4*)(mrow + 3 * RS + i4 * 4);
#pragma unroll
                for (int j = 0; j < 4; j++) {
                    const ulonglong2 w01 =
                        *(const ulonglong2*)(swg1 + (i4 * 4 + j) * 64 + c0);
                    const ulonglong2 w23 =
                        *(const ulonglong2*)(swg1 + (i4 * 4 + j) * 64 + c0 + 4);
                    u64 d;
                    d = pack2(a0[j]);
                    fma2(acc[0][0], d, w01.x); fma2(acc[0][1], d, w01.y);
                    fma2(acc[0][2], d, w23.x); fma2(acc[0][3], d, w23.y);
                    d = pack2(a1[j]);
                    fma2(acc[1][0], d, w01.x); fma2(acc[1][1], d, w01.y);
                    fma2(acc[1][2], d, w23.x); fma2(acc[1][3], d, w23.y);
                    d = pack2(a2[j]);
                    fma2(acc[2][0], d, w01.x); fma2(acc[2][1], d, w01.y);
                    fma2(acc[2][2], d, w23.x); fma2(acc[2][3], d, w23.y);
                    d = pack2(a3[j]);
                    fma2(acc[3][0], d, w01.x); fma2(acc[3][1], d, w01.y);
                    fma2(acc[3][2], d, w23.x); fma2(acc[3][3], d, w23.y);
                }
            }
            __syncwarp();   // all reads of mbf done before in-place write
            const float4 gA = *(const float4*)(sbias + 256 + c0);
            const float4 gB = *(const float4*)(sbias + 256 + c0 + 4);
            const float4 bA = *(const float4*)(sbias + 320 + c0);
            const float4 bB = *(const float4*)(sbias + 320 + c0 + 4);
#pragma unroll
            for (int jj = 0; jj < 4; jj++) {
                const float2 h01 = unpk(acc[jj][0]);
                const float2 h23 = unpk(acc[jj][1]);
                const float2 h45 = unpk(acc[jj][2]);
                const float2 h67 = unpk(acc[jj][3]);
                float s1 = ((h01.x + h01.y) + (h23.x + h23.y))
                         + ((h45.x + h45.y) + (h67.x + h67.y));
                float s2 = ((h01.x*h01.x + h01.y*h01.y) + (h23.x*h23.x + h23.y*h23.y))
                         + ((h45.x*h45.x + h45.y*h45.y) + (h67.x*h67.x + h67.y*h67.y));
                reduce8(s1, s2);
                const float mean = s1 * 0.015625f;
                const float var  = s2 * 0.015625f - mean * mean;
                const float inv  = rsqrtf(var + LN_EPS);
                float4 o0, o1;
                o0.x = fmaxf(fmaf((h01.x - mean) * inv, gA.x, bA.x), 0.f);
                o0.y = fmaxf(fmaf((h01.y - mean) * inv, gA.y, bA.y), 0.f);
                o0.z = fmaxf(fmaf((h23.x - mean) * inv, gA.z, bA.z), 0.f);
                o0.w = fmaxf(fmaf((h23.y - mean) * inv, gA.w, bA.w), 0.f);
                o1.x = fmaxf(fmaf((h45.x - mean) * inv, gB.x, bB.x), 0.f);
                o1.y = fmaxf(fmaf((h45.y - mean) * inv, gB.y, bB.y), 0.f);
                o1.z = fmaxf(fmaf((h67.x - mean) * inv, gB.z, bB.z), 0.f);
                o1.w = fmaxf(fmaf((h67.y - mean) * inv, gB.w, bB.w), 0.f);
                *(float4*)(mbf + (rg2 * 4 + jj) * RS + c0)     = o0;
                *(float4*)(mbf + (rg2 * 4 + jj) * RS + c0 + 4) = o1;
            }
        }
        __syncwarp();

        // ---- GEMM2: w = h @ wg2 + bg2, packed f32x2 ----
        {
            u64 acc[4][4];
            {
                const ulonglong2 b01 = *(const ulonglong2*)(sbias + 384 + c0);
                const ulonglong2 b23 = *(const ulonglong2*)(sbias + 384 + c0 + 4);
#pragma unroll
                for (int jj = 0; jj < 4; jj++) {
                    acc[jj][0] = b01.x; acc[jj][1] = b01.y;
                    acc[jj][2] = b23.x; acc[jj][3] = b23.y;
                }
            }
#pragma unroll 4
            for (int i4 = 0; i4 < 16; i4++) {
                float a0[4], a1[4], a2[4], a3[4];
                *(float4*)a0 = *(const float4*)(mrow + 0 * RS + i4 * 4);
                *(float4*)a1 = *(const float4*)(mrow + 1 * RS + i4 * 4);
                *(float4*)a2 = *(const float4*)(mrow + 2 * RS + i4 * 4);
                *(float4*)a3 = *(const float4*)(mrow + 3 * RS + i4 * 4);
#pragma unroll
                for (int j = 0; j < 4; j++) {
                    const ulonglong2 w01 =
                        *(const ulonglong2*)(swg2 + (i4 * 4 + j) * 64 + c0);
                    const ulonglong2 w23 =
                        *(const ulonglong2*)(swg2 + (i4 * 4 + j) * 64 + c0 + 4);
                    u64 d;
                    d = pack2(a0[j]);
                    fma2(acc[0][0], d, w01.x); fma2(acc[0][1], d, w01.y);
                    fma2(acc[0][2], d, w23.x); fma2(acc[0][3], d, w23.y);
                    d = pack2(a1[j]);
                    fma2(acc[1][0], d, w01.x); fma2(acc[1][1], d, w01.y);
                    fma2(acc[1][2], d, w23.x); fma2(acc[1][3], d, w23.y);
                    d = pack2(a2[j]);
                    fma2(acc[2][0], d, w01.x); fma2(acc[2][1], d, w01.y);
                    fma2(acc[2][2], d, w23.x); fma2(acc[2][3], d, w23.y);
                    d = pack2(a3[j]);
                    fma2(acc[3][0], d, w01.x); fma2(acc[3][1], d, w01.y);
                    fma2(acc[3][2], d, w23.x); fma2(acc[3][3], d, w23.y);
                }
            }
            __syncwarp();
#pragma unroll
            for (int jj = 0; jj < 4; jj++) {
                ulonglong2 s0; s0.x = acc[jj][0]; s0.y = acc[jj][1];
                ulonglong2 s1; s1.x = acc[jj][2]; s1.y = acc[jj][3];
                *(ulonglong2*)(mbf + (rg2 * 4 + jj) * RS + c0)     = s0;
                *(ulonglong2*)(mbf + (rg2 * 4 + jj) * RS + c0 + 4) = s1;
            }
        }
        __syncwarp();

        // ---- softmax over K + weighted sum; thread owns cols u, u+32 ----
        {
            float mx0 = -3.4e38f, mx1 = -3.4e38f;
#pragma unroll
            for (int kk = 0; kk < 16; kk++) {
                mx0 = fmaxf(mx0, mbf[kk * RS + u]);
                mx1 = fmaxf(mx1, mbf[kk * RS + u + 32]);
            }
            float s0 = 0.f, s1 = 0.f, o0 = 0.f, o1 = 0.f;
#pragma unroll
            for (int kk = 0; kk < 16; kk++) {
                const float e0 = __expf(mbf[kk * RS + u] - mx0);
                const float e1 = __expf(mbf[kk * RS + u + 32] - mx1);
                s0 += e0; s1 += e1;
                o0 = fmaf(e0, mgvp[kk * RS + u], o0);
                o1 = fmaf(e1, mgvp[kk * RS + u + 32], o1);
            }
            smout[(pass * 8 + w) * 64 + u]      = __fdividef(o0, s0);
            smout[(pass * 8 + w) * 64 + u + 32] = __fdividef(o1, s1);
        }
        __syncwarp();
    }
    __syncthreads();

    // ---- batched final: out = mout @ wo + bo + residual (16 points) ----
    {
        const int row = t >> 4;
        const int cf  = (t & 15) << 2;
        const int n2 = blockIdx.x * 16 + row;
        float acc3[4];
#pragma unroll
        for (int j = 0; j < 4; j++) acc3[j] = sbias[448 + cf + j];
        const float* morow = smout + row * 64;
#pragma unroll 4
        for (int i4 = 0; i4 < 16; i4++) {
            float a[4];
            *(float4*)a = *(const float4*)(morow + i4 * 4);
#pragma unroll
            for (int j = 0; j < 4; j++) {
                const float4 w4 = *(const float4*)(wo + (i4 * 4 + j) * 64 + cf);
                acc3[0] = fmaf(a[j], w4.x, acc3[0]);
                acc3[1] = fmaf(a[j], w4.y, acc3[1]);
                acc3[2] = fmaf(a[j], w4.z, acc3[2]);
                acc3[3] = fmaf(a[j], w4.w, acc3[3]);
            }
        }
        if (n2 < N) {
            const float4 f4 = *(const float4*)(feat + n2 * 64 + cf);
            *(float4*)(out + n2 * 64 + cf) =
                make_float4(acc3[0] + f4.x, acc3[1] + f4.y,
                            acc3[2] + f4.z, acc3[3] + f4.w);
        }
    }
}

// ---------------------------------------------------------------------------
extern "C" void kernel_launch(void* const* d_in, const int* in_sizes, int n_in,
                              void* d_out, int out_size)
{
    const float* points = (const float*)d_in[0];
    const float* feat   = (const float*)d_in[1];
    const int*   nbr    = (const int*)  d_in[2];
    const float* wq     = (const float*)d_in[3];
    const float* bq     = (const float*)d_in[4];
    const float* wk     = (const float*)d_in[5];
    const float* bk     = (const float*)d_in[6];
    const float* wv     = (const float*)d_in[7];
    const float* bv     = (const float*)d_in[8];
    const float* wp     = (const float*)d_in[9];
    const float* bp     = (const float*)d_in[10];
    const float* gp     = (const float*)d_in[11];
    const float* betap  = (const float*)d_in[12];
    const float* wg1    = (const float*)d_in[13];
    const float* bg1    = (const float*)d_in[14];
    const float* gg     = (const float*)d_in[15];
    const float* betag  = (const float*)d_in[16];
    const float* wg2    = (const float*)d_in[17];
    const float* bg2    = (const float*)d_in[18];
    const float* wo     = (const float*)d_in[19];
    const float* bo     = (const float*)d_in[20];
    float* out = (float*)d_out;

    const int N = in_sizes[0] / 3;

    const int smemA = (3 * 4096 + 192 + 128 * RS) * 4;
    const int smemB = (2 * 4096 + 192 + 512 + 32 + 2 * 8 * 16 * RS + 1024) * 4;
    cudaFuncSetAttribute(qkv_kernel,
                         cudaFuncAttributeMaxDynamicSharedMemorySize, smemA);
    cudaFuncSetAttribute(pt_kernel,
                         cudaFuncAttributeMaxDynamicSharedMemorySize, smemB);

    qkv_kernel<<<(N + 127) / 128, 256, smemA>>>(feat, N, wq, bq, wk, bk, wv, bv);
    pt_kernel<<<(N + 15) / 16, 256, smemB>>>(points, feat, nbr, N,
                                             wp, wg1, wg2, wo,
                                             bp, gp, betap, bg1, gg, betag,
                                             bg2, bo, out);
}

// round 4
// speedup vs baseline: 1.2592x; 1.2592x over previous
#include <cuda_runtime.h>

#define NMAX 50176
#define LN_EPS 1e-5f

__device__ float g_q[NMAX * 64];
__device__ float g_k[NMAX * 64];
__device__ float g_v[NMAX * 64];

typedef unsigned long long u64;

__device__ __forceinline__ u64 pack2(float x) {
    u64 r; asm("mov.b64 %0, {%1, %1};" : "=l"(r) : "f"(x)); return r;
}
__device__ __forceinline__ float2 unpk(u64 v) {
    float2 f; asm("mov.b64 {%0, %1}, %2;" : "=f"(f.x), "=f"(f.y) : "l"(v));
    return f;
}
__device__ __forceinline__ void fma2(u64& d, u64 a, u64 b) {
    asm("fma.rn.f32x2 %0, %1, %2, %0;" : "+l"(d) : "l"(a), "l"(b));
}
__device__ __forceinline__ void reduce16(float& a, float& b) {
#pragma unroll
    for (int off = 8; off > 0; off >>= 1) {
        a += __shfl_xor_sync(0xffffffffu, a, off, 16);
        b += __shfl_xor_sync(0xffffffffu, b, off, 16);
    }
}

#define RSA 68   // qkv feature-tile row stride

// ---------------------------------------------------------------------------
// Kernel A: q/k/v = feat @ W + b. 256 threads, 128 rows/block, 3 passes,
// tile 4 rows x 8 cols, packed f32x2 (round-3 version; measured good).
// ---------------------------------------------------------------------------
__global__ __launch_bounds__(256, 2) void qkv_kernel(
    const float* __restrict__ feat, int N,
    const float* __restrict__ wq, const float* __restrict__ bq,
    const float* __restrict__ wk, const float* __restrict__ bk,
    const float* __restrict__ wv, const float* __restrict__ bv)
{
    extern __shared__ float sm[];
    float* swq = sm;
    float* swk = swq + 4096;
    float* swv = swk + 4096;
    float* sb  = swv + 4096;      // 192
    float* sf  = sb + 192;        // 128 x RSA

    const int t = threadIdx.x;
    for (int j = t; j < 4096; j += 256) {
        swq[j] = wq[j]; swk[j] = wk[j]; swv[j] = wv[j];
    }
    if (t < 64) { sb[t] = bq[t]; sb[64 + t] = bk[t]; sb[128 + t] = bv[t]; }

    const int row0 = blockIdx.x * 128;
    for (int j = t; j < 2048; j += 256) {
        const int row = j >> 4, c4 = (j & 15) << 2;
        float4 f4 = make_float4(0.f, 0.f, 0.f, 0.f);
        if (row0 + row < N) f4 = *(const float4*)(feat + (row0 + row) * 64 + c4);
        *(float4*)(sf + row * RSA + c4) = f4;
    }
    __syncthreads();

    const int rg = t >> 3;
    const int c0 = (t & 7) << 3;
    const float* fr = sf + rg * 4 * RSA;

    const float* Ws[3] = { swq, swk, swv };
    float*       Gs[3] = { g_q, g_k, g_v };

#pragma unroll 1
    for (int m = 0; m < 3; m++) {
        const float* W = Ws[m];
        u64 acc[4][4];
        {
            const ulonglong2 b01 = *(const ulonglong2*)(sb + m * 64 + c0);
            const ulonglong2 b23 = *(const ulonglong2*)(sb + m * 64 + c0 + 4);
#pragma unroll
            for (int jj = 0; jj < 4; jj++) {
                acc[jj][0] = b01.x; acc[jj][1] = b01.y;
                acc[jj][2] = b23.x; acc[jj][3] = b23.y;
            }
        }
#pragma unroll 4
        for (int i4 = 0; i4 < 16; i4++) {
            float a0[4], a1[4], a2[4], a3[4];
            *(float4*)a0 = *(const float4*)(fr + 0 * RSA + i4 * 4);
            *(float4*)a1 = *(const float4*)(fr + 1 * RSA + i4 * 4);
            *(float4*)a2 = *(const float4*)(fr + 2 * RSA + i4 * 4);
            *(float4*)a3 = *(const float4*)(fr + 3 * RSA + i4 * 4);
#pragma unroll
            for (int j = 0; j < 4; j++) {
                const ulonglong2 w01 =
                    *(const ulonglong2*)(W + (i4 * 4 + j) * 64 + c0);
                const ulonglong2 w23 =
                    *(const ulonglong2*)(W + (i4 * 4 + j) * 64 + c0 + 4);
                u64 d;
                d = pack2(a0[j]);
                fma2(acc[0][0], d, w01.x); fma2(acc[0][1], d, w01.y);
                fma2(acc[0][2], d, w23.x); fma2(acc[0][3], d, w23.y);
                d = pack2(a1[j]);
                fma2(acc[1][0], d, w01.x); fma2(acc[1][1], d, w01.y);
                fma2(acc[1][2], d, w23.x); fma2(acc[1][3], d, w23.y);
                d = pack2(a2[j]);
                fma2(acc[2][0], d, w01.x); fma2(acc[2][1], d, w01.y);
                fma2(acc[2][2], d, w23.x); fma2(acc[2][3], d, w23.y);
                d = pack2(a3[j]);
                fma2(acc[3][0], d, w01.x); fma2(acc[3][1], d, w01.y);
                fma2(acc[3][2], d, w23.x); fma2(acc[3][3], d, w23.y);
            }
        }
        float* G = Gs[m];
#pragma unroll
        for (int jj = 0; jj < 4; jj++) {
            const int row = row0 + rg * 4 + jj;
            if (row < N) {
                ulonglong2 s0; s0.x = acc[jj][0]; s0.y = acc[jj][1];
                ulonglong2 s1; s1.x = acc[jj][2]; s1.y = acc[jj][3];
                *(ulonglong2*)(G + row * 64 + c0)     = s0;
                *(ulonglong2*)(G + row * 64 + c0 + 4) = s1;
            }
        }
    }
}

// ---------------------------------------------------------------------------
// Kernel B: fused point transformer — round-2 structure (256 thr = 4 groups
// of 64, 4 iters, 64-float rows, 72.5KB smem, 3 CTA/SM) with the GEMM inner
// loops converted to packed f32x2 (same LDS count, half the FMA-pipe load).
// ---------------------------------------------------------------------------
__global__ __launch_bounds__(256, 3) void pt_kernel(
    const float* __restrict__ points, const float* __restrict__ feat,
    const int* __restrict__ nbr, int N,
    const float* __restrict__ wp,  const float* __restrict__ wg1,
    const float* __restrict__ wg2, const float* __restrict__ wo,
    const float* __restrict__ bp,  const float* __restrict__ gp,
    const float* __restrict__ betap,
    const float* __restrict__ bg1, const float* __restrict__ gg,
    const float* __restrict__ betag,
    const float* __restrict__ bg2, const float* __restrict__ bo,
    float* __restrict__ out)
{
    extern __shared__ float sm[];
    float* swg1  = sm;               // 4096
    float* swg2  = swg1 + 4096;      // 4096
    float* swp   = swg2 + 4096;      // 192
    float* sbias = swp  + 192;       // 512
    float* sM    = sbias + 512;      // 32
    float* sgvp  = sM    + 32;       // 4 x 1024
    float* sbf   = sgvp  + 4096;     // 4 x 1024
    float* smout = sbf   + 4096;     // 16 x 64

    const int t = threadIdx.x;
    for (int j = t; j < 4096; j += 256) { swg1[j] = wg1[j]; swg2[j] = wg2[j]; }
    for (int j = t; j < 192; j += 256) swp[j] = wp[j];
    if (t < 64) {
        sbias[t]       = bp[t];
        sbias[64 + t]  = gp[t];
        sbias[128 + t] = betap[t];
        sbias[192 + t] = bg1[t];
        sbias[256 + t] = gg[t];
        sbias[320 + t] = betag[t];
        sbias[384 + t] = bg2[t];
        sbias[448 + t] = bo[t];
    }
    __syncthreads();

    if (t < 20) {   // Gram matrix of [wp0,wp1,wp2,bp] for analytic pos-LN
        if (t < 16) {
            const int a = t >> 2, b = t & 3;
            const float* ra = (a < 3) ? (swp + a * 64) : sbias;
            const float* rb = (b < 3) ? (swp + b * 64) : sbias;
            float s = 0.f;
            for (int c = 0; c < 64; c++) s += ra[c] * rb[c];
            sM[t] = s;
        } else {
            const int a = t - 16;
            const float* ra = (a < 3) ? (swp + a * 64) : sbias;
            float s = 0.f;
            for (int c = 0; c < 64; c++) s += ra[c];
            sM[t] = s;
        }
    }
    __syncthreads();

    const int pg = t >> 6;
    const int u  = t & 63;
    const int rq = u >> 4;          // rows rq*4..+3
    const int c0 = (u & 15) << 2;   // cols c0..c0+3

    float* mgvp = sgvp + pg * 1024;
    float* mbf  = sbf  + pg * 1024;
    const float* mrow = mbf + (rq * 4) * 64;

    const float4 wpx = *(const float4*)(swp + c0);
    const float4 wpy = *(const float4*)(swp + 64 + c0);
    const float4 wpz = *(const float4*)(swp + 128 + c0);
    const float4 bp4 = *(const float4*)(sbias + c0);
    const float4 gp4 = *(const float4*)(sbias + 64 + c0);
    const float4 bt4 = *(const float4*)(sbias + 128 + c0);

    for (int iter = 0; iter < 4; iter++) {
        const int n = blockIdx.x * 16 + iter * 4 + pg;
        const bool valid = (n < N);
        const int nn = valid ? n : 0;

        const float4 q4 = *(const float4*)(g_q + nn * 64 + c0);
        const float ptx = points[nn * 3 + 0];
        const float pty = points[nn * 3 + 1];
        const float ptz = points[nn * 3 + 2];

        // --- gather + positional LN/relu (analytic stats) + attn_in ---
#pragma unroll
        for (int jj = 0; jj < 4; jj++) {
            const int r = rq * 4 + jj;
            const int id = nbr[nn * 16 + r];
            const float rx = points[id * 3 + 0] - ptx;
            const float ry = points[id * 3 + 1] - pty;
            const float rz = points[id * 3 + 2] - ptz;

            const float s1 = fmaf(rx, sM[16], fmaf(ry, sM[17],
                             fmaf(rz, sM[18], sM[19])));
            const float tx = fmaf(rx, sM[0],  fmaf(ry, sM[1],
                             fmaf(rz, sM[2],  sM[3])));
            const float ty = fmaf(rx, sM[4],  fmaf(ry, sM[5],
                             fmaf(rz, sM[6],  sM[7])));
            const float tz = fmaf(rx, sM[8],  fmaf(ry, sM[9],
                             fmaf(rz, sM[10], sM[11])));
            const float tw = fmaf(rx, sM[12], fmaf(ry, sM[13],
                             fmaf(rz, sM[14], sM[15])));
            const float s2 = fmaf(rx, tx, fmaf(ry, ty, fmaf(rz, tz, tw)));
            const float mean = s1 * 0.015625f;
            const float var  = s2 * 0.015625f - mean * mean;
            const float inv  = rsqrtf(var + LN_EPS);

            float pr[4], pv[4];
            pr[0] = fmaf(rx, wpx.x, fmaf(ry, wpy.x, fmaf(rz, wpz.x, bp4.x)));
            pr[1] = fmaf(rx, wpx.y, fmaf(ry, wpy.y, fmaf(rz, wpz.y, bp4.y)));
            pr[2] = fmaf(rx, wpx.z, fmaf(ry, wpy.z, fmaf(rz, wpz.z, bp4.z)));
            pr[3] = fmaf(rx, wpx.w, fmaf(ry, wpy.w, fmaf(rz, wpz.w, bp4.w)));
            pv[0] = fmaxf(fmaf((pr[0] - mean) * inv, gp4.x, bt4.x), 0.f);
            pv[1] = fmaxf(fmaf((pr[1] - mean) * inv, gp4.y, bt4.y), 0.f);
            pv[2] = fmaxf(fmaf((pr[2] - mean) * inv, gp4.z, bt4.z), 0.f);
            pv[3] = fmaxf(fmaf((pr[3] - mean) * inv, gp4.w, bt4.w), 0.f);

            const float4 gk4 = *(const float4*)(g_k + id * 64 + c0);
            const float4 gv4 = *(const float4*)(g_v + id * 64 + c0);

            *(float4*)(mbf + r * 64 + c0) =
                make_float4(q4.x - gk4.x + pv[0], q4.y - gk4.y + pv[1],
                            q4.z - gk4.z + pv[2], q4.w - gk4.w + pv[3]);
            *(float4*)(mgvp + r * 64 + c0) =
                make_float4(gv4.x + pv[0], gv4.y + pv[1],
                            gv4.z + pv[2], gv4.w + pv[3]);
        }
        __syncwarp();

        // ---- GEMM1: h = relu(LN(attn_in @ wg1 + bg1)), f32x2 ----
        {
            u64 acc[4][2];
            {
                const ulonglong2 b01 = *(const ulonglong2*)(sbias + 192 + c0);
#pragma unroll
                for (int jj = 0; jj < 4; jj++) {
                    acc[jj][0] = b01.x; acc[jj][1] = b01.y;
                }
            }
#pragma unroll 4
            for (int i4 = 0; i4 < 16; i4++) {
                float a0[4], a1[4], a2[4], a3[4];
                *(float4*)a0 = *(const float4*)(mrow + 0 * 64 + i4 * 4);
                *(float4*)a1 = *(const float4*)(mrow + 1 * 64 + i4 * 4);
                *(float4*)a2 = *(const float4*)(mrow + 2 * 64 + i4 * 4);
                *(float4*)a3 = *(const float4*)(mrow + 3 * 64 + i4 * 4);
#pragma unroll
                for (int j = 0; j < 4; j++) {
                    const ulonglong2 w2 =
                        *(const ulonglong2*)(swg1 + (i4 * 4 + j) * 64 + c0);
                    u64 d;
                    d = pack2(a0[j]);
                    fma2(acc[0][0], d, w2.x); fma2(acc[0][1], d, w2.y);
                    d = pack2(a1[j]);
                    fma2(acc[1][0], d, w2.x); fma2(acc[1][1], d, w2.y);
                    d = pack2(a2[j]);
                    fma2(acc[2][0], d, w2.x); fma2(acc[2][1], d, w2.y);
                    d = pack2(a3[j]);
                    fma2(acc[3][0], d, w2.x); fma2(acc[3][1], d, w2.y);
                }
            }
            const float4 gA = *(const float4*)(sbias + 256 + c0);
            const float4 bA = *(const float4*)(sbias + 320 + c0);
            float o[4][4];
#pragma unroll
            for (int jj = 0; jj < 4; jj++) {
                const float2 h01 = unpk(acc[jj][0]);
                const float2 h23 = unpk(acc[jj][1]);
                float s1 = (h01.x + h01.y) + (h23.x + h23.y);
                float s2 = (h01.x*h01.x + h01.y*h01.y)
                         + (h23.x*h23.x + h23.y*h23.y);
                reduce16(s1, s2);
                const float mean = s1 * 0.015625f;
                const float var  = s2 * 0.015625f - mean * mean;
                const float inv  = rsqrtf(var + LN_EPS);
                o[jj][0] = fmaxf(fmaf((h01.x - mean) * inv, gA.x, bA.x), 0.f);
                o[jj][1] = fmaxf(fmaf((h01.y - mean) * inv, gA.y, bA.y), 0.f);
                o[jj][2] = fmaxf(fmaf((h23.x - mean) * inv, gA.z, bA.z), 0.f);
                o[jj][3] = fmaxf(fmaf((h23.y - mean) * inv, gA.w, bA.w), 0.f);
            }
            // reduce16 shfl converged the warp; all mrow reads complete
#pragma unroll
            for (int jj = 0; jj < 4; jj++)
                *(float4*)(mbf + (rq * 4 + jj) * 64 + c0) =
                    make_float4(o[jj][0], o[jj][1], o[jj][2], o[jj][3]);
        }
        __syncwarp();

        // ---- GEMM2: w = h @ wg2 + bg2, f32x2 ----
        {
            u64 acc[4][2];
            {
                const ulonglong2 b01 = *(const ulonglong2*)(sbias + 384 + c0);
#pragma unroll
                for (int jj = 0; jj < 4; jj++) {
                    acc[jj][0] = b01.x; acc[jj][1] = b01.y;
                }
            }
#pragma unroll 4
            for (int i4 = 0; i4 < 16; i4++) {
                float a0[4], a1[4], a2[4], a3[4];
                *(float4*)a0 = *(const float4*)(mrow + 0 * 64 + i4 * 4);
                *(float4*)a1 = *(const float4*)(mrow + 1 * 64 + i4 * 4);
                *(float4*)a2 = *(const float4*)(mrow + 2 * 64 + i4 * 4);
                *(float4*)a3 = *(const float4*)(mrow + 3 * 64 + i4 * 4);
#pragma unroll
                for (int j = 0; j < 4; j++) {
                    const ulonglong2 w2 =
                        *(const ulonglong2*)(swg2 + (i4 * 4 + j) * 64 + c0);
                    u64 d;
                    d = pack2(a0[j]);
                    fma2(acc[0][0], d, w2.x); fma2(acc[0][1], d, w2.y);
                    d = pack2(a1[j]);
                    fma2(acc[1][0], d, w2.x); fma2(acc[1][1], d, w2.y);
                    d = pack2(a2[j]);
                    fma2(acc[2][0], d, w2.x); fma2(acc[2][1], d, w2.y);
                    d = pack2(a3[j]);
                    fma2(acc[3][0], d, w2.x); fma2(acc[3][1], d, w2.y);
                }
            }
            __syncwarp();
#pragma unroll
            for (int jj = 0; jj < 4; jj++) {
                ulonglong2 s0; s0.x = acc[jj][0]; s0.y = acc[jj][1];
                *(ulonglong2*)(mbf + (rq * 4 + jj) * 64 + c0) = s0;
            }
        }
        __syncthreads();   // softmax reads columns across all warps

        // ---- softmax over K + weighted sum; thread u owns column u ----
        float mx = -3.4e38f;
#pragma unroll
        for (int kk = 0; kk < 16; kk++) mx = fmaxf(mx, mbf[kk * 64 + u]);
        float s = 0.f, o = 0.f;
#pragma unroll
        for (int kk = 0; kk < 16; kk++) {
            const float e = __expf(mbf[kk * 64 + u] - mx);
            s += e;
            o = fmaf(e, mgvp[kk * 64 + u], o);
        }
        smout[(iter * 4 + pg) * 64 + u] = __fdividef(o, s);
        __syncthreads();
    }

    // ---- batched final: out = mout @ wo + bo + residual (16 points) ----
    {
        const int row = t >> 4;
        const int cf  = (t & 15) << 2;
        const int n2 = blockIdx.x * 16 + row;
        u64 acc[2];
        {
            const ulonglong2 b01 = *(const ulonglong2*)(sbias + 448 + cf);
            acc[0] = b01.x; acc[1] = b01.y;
        }
        const float* morow = smout + row * 64;
#pragma unroll 4
        for (int i4 = 0; i4 < 16; i4++) {
            float a[4];
            *(float4*)a = *(const float4*)(morow + i4 * 4);
#pragma unroll
            for (int j = 0; j < 4; j++) {
                const ulonglong2 w2 =
                    *(const ulonglong2*)(wo + (i4 * 4 + j) * 64 + cf);
                const u64 d = pack2(a[j]);
                fma2(acc[0], d, w2.x); fma2(acc[1], d, w2.y);
            }
        }
        if (n2 < N) {
            const float2 r01 = unpk(acc[0]);
            const float2 r23 = unpk(acc[1]);
            const float4 f4 = *(const float4*)(feat + n2 * 64 + cf);
            *(float4*)(out + n2 * 64 + cf) =
                make_float4(r01.x + f4.x, r01.y + f4.y,
                            r23.x + f4.z, r23.y + f4.w);
        }
    }
}

// ---------------------------------------------------------------------------
extern "C" void kernel_launch(void* const* d_in, const int* in_sizes, int n_in,
                              void* d_out, int out_size)
{
    const float* points = (const float*)d_in[0];
    const float* feat   = (const float*)d_in[1];
    const int*   nbr    = (const int*)  d_in[2];
    const float* wq     = (const float*)d_in[3];
    const float* bq     = (const float*)d_in[4];
    const float* wk     = (const float*)d_in[5];
    const float* bk     = (const float*)d_in[6];
    const float* wv     = (const float*)d_in[7];
    const float* bv     = (const float*)d_in[8];
    const float* wp     = (const float*)d_in[9];
    const float* bp     = (const float*)d_in[10];
    const float* gp     = (const float*)d_in[11];
    const float* betap  = (const float*)d_in[12];
    const float* wg1    = (const float*)d_in[13];
    const float* bg1    = (const float*)d_in[14];
    const float* gg     = (const float*)d_in[15];
    const float* betag  = (const float*)d_in[16];
    const float* wg2    = (const float*)d_in[17];
    const float* bg2    = (const float*)d_in[18];
    const float* wo     = (const float*)d_in[19];
    const float* bo     = (const float*)d_in[20];
    float* out = (float*)d_out;

    const int N = in_sizes[0] / 3;

    const int smemA = (3 * 4096 + 192 + 128 * RSA) * 4;
    const int smemB = (2 * 4096 + 192 + 512 + 32 + 2 * 4096 + 1024) * 4; // 72576
    cudaFuncSetAttribute(qkv_kernel,
                         cudaFuncAttributeMaxDynamicSharedMemorySize, smemA);
    cudaFuncSetAttribute(pt_kernel,
                         cudaFuncAttributeMaxDynamicSharedMemorySize, smemB);

    qkv_kernel<<<(N + 127) / 128, 256, smemA>>>(feat, N, wq, bq, wk, bk, wv, bv);
    pt_kernel<<<(N + 15) / 16, 256, smemB>>>(points, feat, nbr, N,
                                             wp, wg1, wg2, wo,
                                             bp, gp, betap, bg1, gg, betag,
                                             bg2, bo, out);
}

// round 6
// speedup vs baseline: 1.9665x; 1.5617x over previous
#include <cuda_runtime.h>
#include <cuda_bf16.h>

#define NMAX 50176
#define LN_EPS 1e-5f

__device__ float g_q[NMAX * 64];
__device__ float g_k[NMAX * 64];
__device__ float g_v[NMAX * 64];

// prebuilt B fragments: [gemm(2)][term(2)][ntile(8)][ktile(4)][lane(32)] uint2
__device__ uint2 g_bfrag[4096];
__device__ float g_gram[20];

typedef unsigned long long u64;
typedef unsigned int u32;

__device__ __forceinline__ u64 pack2f(float x) {
    u64 r; asm("mov.b64 %0, {%1, %1};" : "=l"(r) : "f"(x)); return r;
}
__device__ __forceinline__ void fma2(u64& d, u64 a, u64 b) {
    asm("fma.rn.f32x2 %0, %1, %2, %0;" : "+l"(d) : "l"(a), "l"(b));
}

// split (x,y) into packed bf16x2 hi and lo parts
__device__ __forceinline__ void bsplit2(float x, float y, u32& hp, u32& lp) {
    __nv_bfloat16 bx = __float2bfloat16_rn(x);
    __nv_bfloat16 by = __float2bfloat16_rn(y);
    float rx = x - __bfloat162float(bx);
    float ry = y - __bfloat162float(by);
    __nv_bfloat16 cx = __float2bfloat16_rn(rx);
    __nv_bfloat16 cy = __float2bfloat16_rn(ry);
    hp = (u32)__bfloat16_as_ushort(bx) | ((u32)__bfloat16_as_ushort(by) << 16);
    lp = (u32)__bfloat16_as_ushort(cx) | ((u32)__bfloat16_as_ushort(cy) << 16);
}

__device__ __forceinline__ void mma16816(float* d, const u32* a, uint2 b) {
    asm volatile(
        "mma.sync.aligned.m16n8k16.row.col.f32.bf16.bf16.f32 "
        "{%0,%1,%2,%3}, {%4,%5,%6,%7}, {%8,%9}, {%0,%1,%2,%3};"
        : "+f"(d[0]), "+f"(d[1]), "+f"(d[2]), "+f"(d[3])
        : "r"(a[0]), "r"(a[1]), "r"(a[2]), "r"(a[3]), "r"(b.x), "r"(b.y));
}

#define RSA 68

// ---------------------------------------------------------------------------
// Init kernel: build B fragments (wg1/wg2, hi/lo) + Gram matrix. One CTA.
// ---------------------------------------------------------------------------
__global__ void build_kernel(const float* __restrict__ wg1,
                             const float* __restrict__ wg2,
                             const float* __restrict__ wp,
                             const float* __restrict__ bp)
{
    const int t = threadIdx.x;   // 256
    for (int e = t; e < 4096; e += 256) {
        const int lane = e & 31;
        const int kt   = (e >> 5) & 3;
        const int j    = (e >> 7) & 7;
        const int tau  = (e >> 10) & 1;
        const int g    = (e >> 11) & 1;
        const float* W = g ? wg2 : wg1;
        const int n  = 8 * j + (lane >> 2);
        const int k0 = 16 * kt + 2 * (lane & 3);
        // b0 = {W[k0][n], W[k0+1][n]}, b1 = {W[k0+8][n], W[k0+9][n]}
        u32 h0, l0, h1, l1;
        bsplit2(W[k0 * 64 + n],       W[(k0 + 1) * 64 + n], h0, l0);
        bsplit2(W[(k0 + 8) * 64 + n], W[(k0 + 9) * 64 + n], h1, l1);
        uint2 r;
        r.x = tau ? l0 : h0;
        r.y = tau ? l1 : h1;
        g_bfrag[e] = r;
    }
    if (t < 20) {
        if (t < 16) {
            const int a = t >> 2, b = t & 3;
            const float* ra = (a < 3) ? (wp + a * 64) : bp;
            const float* rb = (b < 3) ? (wp + b * 64) : bp;
            float s = 0.f;
            for (int c = 0; c < 64; c++) s += ra[c] * rb[c];
            g_gram[t] = s;
        } else {
            const int a = t - 16;
            const float* ra = (a < 3) ? (wp + a * 64) : bp;
            float s = 0.f;
            for (int c = 0; c < 64; c++) s += ra[c];
            g_gram[t] = s;
        }
    }
}

// ---------------------------------------------------------------------------
// Kernel A: q/k/v = feat @ W + b (unchanged — measured good)
// ---------------------------------------------------------------------------
__global__ __launch_bounds__(256, 2) void qkv_kernel(
    const float* __restrict__ feat, int N,
    const float* __restrict__ wq, const float* __restrict__ bq,
    const float* __restrict__ wk, const float* __restrict__ bk,
    const float* __restrict__ wv, const float* __restrict__ bv)
{
    extern __shared__ float sm[];
    float* swq = sm;
    float* swk = swq + 4096;
    float* swv = swk + 4096;
    float* sb  = swv + 4096;
    float* sf  = sb + 192;

    const int t = threadIdx.x;
    for (int j = t; j < 4096; j += 256) {
        swq[j] = wq[j]; swk[j] = wk[j]; swv[j] = wv[j];
    }
    if (t < 64) { sb[t] = bq[t]; sb[64 + t] = bk[t]; sb[128 + t] = bv[t]; }

    const int row0 = blockIdx.x * 128;
    for (int j = t; j < 2048; j += 256) {
        const int row = j >> 4, c4 = (j & 15) << 2;
        float4 f4 = make_float4(0.f, 0.f, 0.f, 0.f);
        if (row0 + row < N) f4 = *(const float4*)(feat + (row0 + row) * 64 + c4);
        *(float4*)(sf + row * RSA + c4) = f4;
    }
    __syncthreads();

    const int rg = t >> 3;
    const int c0 = (t & 7) << 3;
    const float* fr = sf + rg * 4 * RSA;

    const float* Ws[3] = { swq, swk, swv };
    float*       Gs[3] = { g_q, g_k, g_v };

#pragma unroll 1
    for (int m = 0; m < 3; m++) {
        const float* W = Ws[m];
        u64 acc[4][4];
        {
            const ulonglong2 b01 = *(const ulonglong2*)(sb + m * 64 + c0);
            const ulonglong2 b23 = *(const ulonglong2*)(sb + m * 64 + c0 + 4);
#pragma unroll
            for (int jj = 0; jj < 4; jj++) {
                acc[jj][0] = b01.x; acc[jj][1] = b01.y;
                acc[jj][2] = b23.x; acc[jj][3] = b23.y;
            }
        }
#pragma unroll 4
        for (int i4 = 0; i4 < 16; i4++) {
            float a0[4], a1[4], a2[4], a3[4];
            *(float4*)a0 = *(const float4*)(fr + 0 * RSA + i4 * 4);
            *(float4*)a1 = *(const float4*)(fr + 1 * RSA + i4 * 4);
            *(float4*)a2 = *(const float4*)(fr + 2 * RSA + i4 * 4);
            *(float4*)a3 = *(const float4*)(fr + 3 * RSA + i4 * 4);
#pragma unroll
            for (int j = 0; j < 4; j++) {
                const ulonglong2 w01 =
                    *(const ulonglong2*)(W + (i4 * 4 + j) * 64 + c0);
                const ulonglong2 w23 =
                    *(const ulonglong2*)(W + (i4 * 4 + j) * 64 + c0 + 4);
                u64 d;
                d = pack2f(a0[j]);
                fma2(acc[0][0], d, w01.x); fma2(acc[0][1], d, w01.y);
                fma2(acc[0][2], d, w23.x); fma2(acc[0][3], d, w23.y);
                d = pack2f(a1[j]);
                fma2(acc[1][0], d, w01.x); fma2(acc[1][1], d, w01.y);
                fma2(acc[1][2], d, w23.x); fma2(acc[1][3], d, w23.y);
                d = pack2f(a2[j]);
                fma2(acc[2][0], d, w01.x); fma2(acc[2][1], d, w01.y);
                fma2(acc[2][2], d, w23.x); fma2(acc[2][3], d, w23.y);
                d = pack2f(a3[j]);
                fma2(acc[3][0], d, w01.x); fma2(acc[3][1], d, w01.y);
                fma2(acc[3][2], d, w23.x); fma2(acc[3][3], d, w23.y);
            }
        }
        float* G = Gs[m];
#pragma unroll
        for (int jj = 0; jj < 4; jj++) {
            const int row = row0 + rg * 4 + jj;
            if (row < N) {
                ulonglong2 s0; s0.x = acc[jj][0]; s0.y = acc[jj][1];
                ulonglong2 s1; s1.x = acc[jj][2]; s1.y = acc[jj][3];
                *(ulonglong2*)(G + row * 64 + c0)     = s0;
                *(ulonglong2*)(G + row * 64 + c0 + 4) = s1;
            }
        }
    }
}

// ---------------------------------------------------------------------------
// Kernel B: one warp per point via mma.sync m16n8k16 bf16 (hi/lo split).
// 128 threads = 4 warps = 4 points per CTA. Fully register-resident chain.
// ---------------------------------------------------------------------------
__global__ __launch_bounds__(128, 3) void pt_mma_kernel(
    const float* __restrict__ points, const float* __restrict__ feat,
    const int* __restrict__ nbr, int N,
    const float* __restrict__ wp,  const float* __restrict__ wo,
    const float* __restrict__ bp,  const float* __restrict__ gp,
    const float* __restrict__ betap,
    const float* __restrict__ bg1, const float* __restrict__ gg,
    const float* __restrict__ betag,
    const float* __restrict__ bo,
    float* __restrict__ out)
{
    __shared__ float mout[4][64];

    const int t = threadIdx.x;
    const int lane = t & 31;
    const int warp = t >> 5;

    int n = blockIdx.x * 4 + warp;
    if (n >= N) n = N - 1;

    const int base = 2 * (lane & 3);   // column pair base
    const int r1 = lane >> 2;          // neighbor rows r1, r1+8

    // Gram matrix for analytic positional LN
    float M[20];
#pragma unroll
    for (int i = 0; i < 20; i++) M[i] = __ldg(&g_gram[i]);

    // ---- neighbor geometry + analytic LN stats for both rows ----
    const int id1 = __ldg(&nbr[n * 16 + r1]);
    const int id2 = __ldg(&nbr[n * 16 + r1 + 8]);
    const float px = __ldg(&points[n * 3 + 0]);
    const float py = __ldg(&points[n * 3 + 1]);
    const float pz = __ldg(&points[n * 3 + 2]);
    const float rx1 = __ldg(&points[id1 * 3 + 0]) - px;
    const float ry1 = __ldg(&points[id1 * 3 + 1]) - py;
    const float rz1 = __ldg(&points[id1 * 3 + 2]) - pz;
    const float rx2 = __ldg(&points[id2 * 3 + 0]) - px;
    const float ry2 = __ldg(&points[id2 * 3 + 1]) - py;
    const float rz2 = __ldg(&points[id2 * 3 + 2]) - pz;

    float mean1, inv1, mean2, inv2;
    {
        const float s1 = fmaf(rx1, M[16], fmaf(ry1, M[17], fmaf(rz1, M[18], M[19])));
        const float tx = fmaf(rx1, M[0],  fmaf(ry1, M[1],  fmaf(rz1, M[2],  M[3])));
        const float ty = fmaf(rx1, M[4],  fmaf(ry1, M[5],  fmaf(rz1, M[6],  M[7])));
        const float tz = fmaf(rx1, M[8],  fmaf(ry1, M[9],  fmaf(rz1, M[10], M[11])));
        const float tw = fmaf(rx1, M[12], fmaf(ry1, M[13], fmaf(rz1, M[14], M[15])));
        const float s2 = fmaf(rx1, tx, fmaf(ry1, ty, fmaf(rz1, tz, tw)));
        mean1 = s1 * 0.015625f;
        inv1 = rsqrtf(s2 * 0.015625f - mean1 * mean1 + LN_EPS);
    }
    {
        const float s1 = fmaf(rx2, M[16], fmaf(ry2, M[17], fmaf(rz2, M[18], M[19])));
        const float tx = fmaf(rx2, M[0],  fmaf(ry2, M[1],  fmaf(rz2, M[2],  M[3])));
        const float ty = fmaf(rx2, M[4],  fmaf(ry2, M[5],  fmaf(rz2, M[6],  M[7])));
        const float tz = fmaf(rx2, M[8],  fmaf(ry2, M[9],  fmaf(rz2, M[10], M[11])));
        const float tw = fmaf(rx2, M[12], fmaf(ry2, M[13], fmaf(rz2, M[14], M[15])));
        const float s2 = fmaf(rx2, tx, fmaf(ry2, ty, fmaf(rz2, tz, tw)));
        mean2 = s1 * 0.015625f;
        inv2 = rsqrtf(s2 * 0.015625f - mean2 * mean2 + LN_EPS);
    }

    // ---- gather + positional LN/relu -> A fragments (bf16 hi/lo) + gv+p ----
    u32 aHi[16], aLo[16];      // [kt*4 + reg]
    float gv1[16], gv2[16];    // [2m + {0,1}] rows r1 / r1+8
#pragma unroll
    for (int m = 0; m < 8; m++) {
        const int c = 8 * m + base;
        const float2 q2 = *(const float2*)(g_q + n * 64 + c);
        const float2 k1 = *(const float2*)(g_k + id1 * 64 + c);
        const float2 k2 = *(const float2*)(g_k + id2 * 64 + c);
        const float2 v1 = *(const float2*)(g_v + id1 * 64 + c);
        const float2 v2 = *(const float2*)(g_v + id2 * 64 + c);
        const float2 wx = __ldg((const float2*)(wp + c));
        const float2 wy = __ldg((const float2*)(wp + 64 + c));
        const float2 wz = __ldg((const float2*)(wp + 128 + c));
        const float2 b2 = __ldg((const float2*)(bp + c));
        const float2 g2 = __ldg((const float2*)(gp + c));
        const float2 e2 = __ldg((const float2*)(betap + c));

        const float pA0 = fmaf(rx1, wx.x, fmaf(ry1, wy.x, fmaf(rz1, wz.x, b2.x)));
        const float pA1 = fmaf(rx1, wx.y, fmaf(ry1, wy.y, fmaf(rz1, wz.y, b2.y)));
        const float pB0 = fmaf(rx2, wx.x, fmaf(ry2, wy.x, fmaf(rz2, wz.x, b2.x)));
        const float pB1 = fmaf(rx2, wx.y, fmaf(ry2, wy.y, fmaf(rz2, wz.y, b2.y)));
        const float vA0 = fmaxf(fmaf((pA0 - mean1) * inv1, g2.x, e2.x), 0.f);
        const float vA1 = fmaxf(fmaf((pA1 - mean1) * inv1, g2.y, e2.y), 0.f);
        const float vB0 = fmaxf(fmaf((pB0 - mean2) * inv2, g2.x, e2.x), 0.f);
        const float vB1 = fmaxf(fmaf((pB1 - mean2) * inv2, g2.y, e2.y), 0.f);

        gv1[2 * m]     = v1.x + vA0;  gv1[2 * m + 1] = v1.y + vA1;
        gv2[2 * m]     = v2.x + vB0;  gv2[2 * m + 1] = v2.y + vB1;

        const int kt = m >> 1;
        const int ro = (m & 1) << 1;   // 0 -> regs a0/a1, 1 -> a2/a3
        bsplit2(q2.x - k1.x + vA0, q2.y - k1.y + vA1,
                aHi[kt * 4 + ro], aLo[kt * 4 + ro]);
        bsplit2(q2.x - k2.x + vB0, q2.y - k2.y + vB1,
                aHi[kt * 4 + ro + 1], aLo[kt * 4 + ro + 1]);
    }

    // ---- GEMM1: d = attn @ wg1 (3-term split) ----
    float d[8][4];
#pragma unroll
    for (int j = 0; j < 8; j++)
#pragma unroll
        for (int i = 0; i < 4; i++) d[j][i] = 0.f;
#pragma unroll
    for (int kt = 0; kt < 4; kt++) {
#pragma unroll
        for (int j = 0; j < 8; j++) {
            const uint2 bh = __ldg(&g_bfrag[(j * 4 + kt) * 32 + lane]);
            const uint2 bl = __ldg(&g_bfrag[1024 + (j * 4 + kt) * 32 + lane]);
            mma16816(d[j], &aHi[kt * 4], bh);
            mma16816(d[j], &aLo[kt * 4], bh);
            mma16816(d[j], &aHi[kt * 4], bl);
        }
    }

    // ---- LN + relu over rows (4-lane groups) ----
    {
        float s1a = 0.f, s2a = 0.f, s1b = 0.f, s2b = 0.f;
#pragma unroll
        for (int j = 0; j < 8; j++) {
            const float2 bg = __ldg((const float2*)(bg1 + 8 * j + base));
            d[j][0] += bg.x; d[j][1] += bg.y;
            d[j][2] += bg.x; d[j][3] += bg.y;
            s1a += d[j][0] + d[j][1];
            s2a += d[j][0] * d[j][0] + d[j][1] * d[j][1];
            s1b += d[j][2] + d[j][3];
            s2b += d[j][2] * d[j][2] + d[j][3] * d[j][3];
        }
#pragma unroll
        for (int off = 1; off <= 2; off <<= 1) {
            s1a += __shfl_xor_sync(0xffffffffu, s1a, off);
            s2a += __shfl_xor_sync(0xffffffffu, s2a, off);
            s1b += __shfl_xor_sync(0xffffffffu, s1b, off);
            s2b += __shfl_xor_sync(0xffffffffu, s2b, off);
        }
        const float m1 = s1a * 0.015625f;
        const float i1 = rsqrtf(s2a * 0.015625f - m1 * m1 + LN_EPS);
        const float m2 = s1b * 0.015625f;
        const float i2 = rsqrtf(s2b * 0.015625f - m2 * m2 + LN_EPS);
#pragma unroll
        for (int j = 0; j < 8; j++) {
            const int c = 8 * j + base;
            const float2 gA = __ldg((const float2*)(gg + c));
            const float2 bA = __ldg((const float2*)(betag + c));
            d[j][0] = fmaxf(fmaf((d[j][0] - m1) * i1, gA.x, bA.x), 0.f);
            d[j][1] = fmaxf(fmaf((d[j][1] - m1) * i1, gA.y, bA.y), 0.f);
            d[j][2] = fmaxf(fmaf((d[j][2] - m2) * i2, gA.x, bA.x), 0.f);
            d[j][3] = fmaxf(fmaf((d[j][3] - m2) * i2, gA.y, bA.y), 0.f);
        }
    }

    // ---- repack h into A fragments (D layout == A layout) ----
#pragma unroll
    for (int kt = 0; kt < 4; kt++) {
        bsplit2(d[2 * kt][0],     d[2 * kt][1],     aHi[kt * 4 + 0], aLo[kt * 4 + 0]);
        bsplit2(d[2 * kt][2],     d[2 * kt][3],     aHi[kt * 4 + 1], aLo[kt * 4 + 1]);
        bsplit2(d[2 * kt + 1][0], d[2 * kt + 1][1], aHi[kt * 4 + 2], aLo[kt * 4 + 2]);
        bsplit2(d[2 * kt + 1][2], d[2 * kt + 1][3], aHi[kt * 4 + 3], aLo[kt * 4 + 3]);
    }

    // ---- GEMM2: w = h @ wg2 (bg2 cancels in softmax) ----
    float w[8][4];
#pragma unroll
    for (int j = 0; j < 8; j++)
#pragma unroll
        for (int i = 0; i < 4; i++) w[j][i] = 0.f;
#pragma unroll
    for (int kt = 0; kt < 4; kt++) {
#pragma unroll
        for (int j = 0; j < 8; j++) {
            const uint2 bh = __ldg(&g_bfrag[2048 + (j * 4 + kt) * 32 + lane]);
            const uint2 bl = __ldg(&g_bfrag[3072 + (j * 4 + kt) * 32 + lane]);
            mma16816(w[j], &aHi[kt * 4], bh);
            mma16816(w[j], &aLo[kt * 4], bh);
            mma16816(w[j], &aHi[kt * 4], bl);
        }
    }

    // ---- softmax over 16 neighbors (column = stride-4 lane group) ----
    {
        float mx0[8], mx1[8];
#pragma unroll
        for (int j = 0; j < 8; j++) {
            mx0[j] = fmaxf(w[j][0], w[j][2]);
            mx1[j] = fmaxf(w[j][1], w[j][3]);
        }
#pragma unroll
        for (int off = 4; off <= 16; off <<= 1)
#pragma unroll
            for (int j = 0; j < 8; j++) {
                mx0[j] = fmaxf(mx0[j], __shfl_xor_sync(0xffffffffu, mx0[j], off));
                mx1[j] = fmaxf(mx1[j], __shfl_xor_sync(0xffffffffu, mx1[j], off));
            }
        float s0[8], s1v[8], o0[8], o1[8];
#pragma unroll
        for (int j = 0; j < 8; j++) {
            const float e00 = __expf(w[j][0] - mx0[j]);
            const float e20 = __expf(w[j][2] - mx0[j]);
            const float e11 = __expf(w[j][1] - mx1[j]);
            const float e31 = __expf(w[j][3] - mx1[j]);
            s0[j]  = e00 + e20;
            s1v[j] = e11 + e31;
            o0[j]  = e00 * gv1[2 * j]     + e20 * gv2[2 * j];
            o1[j]  = e11 * gv1[2 * j + 1] + e31 * gv2[2 * j + 1];
        }
#pragma unroll
        for (int off = 4; off <= 16; off <<= 1)
#pragma unroll
            for (int j = 0; j < 8; j++) {
                s0[j]  += __shfl_xor_sync(0xffffffffu, s0[j], off);
                s1v[j] += __shfl_xor_sync(0xffffffffu, s1v[j], off);
                o0[j]  += __shfl_xor_sync(0xffffffffu, o0[j], off);
                o1[j]  += __shfl_xor_sync(0xffffffffu, o1[j], off);
            }
        if (lane < 4) {
#pragma unroll
            for (int j = 0; j < 8; j++) {
                mout[warp][8 * j + base]     = __fdividef(o0[j], s0[j]);
                mout[warp][8 * j + base + 1] = __fdividef(o1[j], s1v[j]);
            }
        }
    }
    __syncthreads();

    // ---- final: out = mout @ wo + bo + residual (f32x2 scalar) ----
    {
        const int p  = t >> 5;
        const int c2 = (t & 31) * 2;
        const int n3 = blockIdx.x * 4 + p;
        u64 acc = *(const u64*)(bo + c2);
        const float* mr = mout[p];
#pragma unroll 8
        for (int k = 0; k < 64; k++) {
            const u64 w2 = __ldg((const u64*)(wo + k * 64 + c2));
            fma2(acc, pack2f(mr[k]), w2);
        }
        if (n3 < N) {
            float r0, r1;
            asm("mov.b64 {%0, %1}, %2;" : "=f"(r0), "=f"(r1) : "l"(acc));
            const float2 f2 = *(const float2*)(feat + n3 * 64 + c2);
            *(float2*)(out + n3 * 64 + c2) = make_float2(r0 + f2.x, r1 + f2.y);
        }
    }
}

// ---------------------------------------------------------------------------
extern "C" void kernel_launch(void* const* d_in, const int* in_sizes, int n_in,
                              void* d_out, int out_size)
{
    const float* points = (const float*)d_in[0];
    const float* feat   = (const float*)d_in[1];
    const int*   nbr    = (const int*)  d_in[2];
    const float* wq     = (const float*)d_in[3];
    const float* bq     = (const float*)d_in[4];
    const float* wk     = (const float*)d_in[5];
    const float* bk     = (const float*)d_in[6];
    const float* wv     = (const float*)d_in[7];
    const float* bv     = (const float*)d_in[8];
    const float* wp     = (const float*)d_in[9];
    const float* bp     = (const float*)d_in[10];
    const float* gp     = (const float*)d_in[11];
    const float* betap  = (const float*)d_in[12];
    const float* wg1    = (const float*)d_in[13];
    const float* bg1    = (const float*)d_in[14];
    const float* gg     = (const float*)d_in[15];
    const float* betag  = (const float*)d_in[16];
    const float* wg2    = (const float*)d_in[17];
    const float* bg2    = (const float*)d_in[18];
    const float* wo     = (const float*)d_in[19];
    const float* bo     = (const float*)d_in[20];
    float* out = (float*)d_out;
    (void)bg2;   // cancels inside softmax

    const int N = in_sizes[0] / 3;

    const int smemA = (3 * 4096 + 192 + 128 * RSA) * 4;
    cudaFuncSetAttribute(qkv_kernel,
                         cudaFuncAttributeMaxDynamicSharedMemorySize, smemA);

    build_kernel<<<1, 256>>>(wg1, wg2, wp, bp);
    qkv_kernel<<<(N + 127) / 128, 256, smemA>>>(feat, N, wq, bq, wk, bk, wv, bv);
    pt_mma_kernel<<<(N + 3) / 4, 128>>>(points, feat, nbr, N,
                                        wp, wo, bp, gp, betap,
                                        bg1, gg, betag, bo, out);
}

// round 7
// speedup vs baseline: 2.1332x; 1.0847x over previous
#include <cuda_runtime.h>
#include <cuda_bf16.h>

#define NMAX 50176
#define LN_EPS 1e-5f

__device__ float g_q[NMAX * 64];
__device__ float g_k[NMAX * 64];
__device__ float g_v[NMAX * 64];

// B fragments: [weight(5: wg1,wg2,wq,wk,wv)][term(2)][j(8)][kt(4)][lane(32)]
__device__ uint2 g_bfrag[10240];
__device__ float g_gram[20];

typedef unsigned long long u64;
typedef unsigned int u32;

__device__ __forceinline__ u64 pack2f(float x) {
    u64 r; asm("mov.b64 %0, {%1, %1};" : "=l"(r) : "f"(x)); return r;
}
__device__ __forceinline__ void fma2(u64& d, u64 a, u64 b) {
    asm("fma.rn.f32x2 %0, %1, %2, %0;" : "+l"(d) : "l"(a), "l"(b));
}
__device__ __forceinline__ void bsplit2(float x, float y, u32& hp, u32& lp) {
    __nv_bfloat16 bx = __float2bfloat16_rn(x);
    __nv_bfloat16 by = __float2bfloat16_rn(y);
    float rx = x - __bfloat162float(bx);
    float ry = y - __bfloat162float(by);
    __nv_bfloat16 cx = __float2bfloat16_rn(rx);
    __nv_bfloat16 cy = __float2bfloat16_rn(ry);
    hp = (u32)__bfloat16_as_ushort(bx) | ((u32)__bfloat16_as_ushort(by) << 16);
    lp = (u32)__bfloat16_as_ushort(cx) | ((u32)__bfloat16_as_ushort(cy) << 16);
}
__device__ __forceinline__ void mma16816(float* d, const u32* a, uint2 b) {
    asm volatile(
        "mma.sync.aligned.m16n8k16.row.col.f32.bf16.bf16.f32 "
        "{%0,%1,%2,%3}, {%4,%5,%6,%7}, {%8,%9}, {%0,%1,%2,%3};"
        : "+f"(d[0]), "+f"(d[1]), "+f"(d[2]), "+f"(d[3])
        : "r"(a[0]), "r"(a[1]), "r"(a[2]), "r"(a[3]), "r"(b.x), "r"(b.y));
}

// ---------------------------------------------------------------------------
// Init: build B fragments for all 5 weights + Gram matrix. 41 CTAs.
// entry layout: e = wi*2048 + tau*1024 + j*128 + kt*32 + lane
// ---------------------------------------------------------------------------
__global__ void build_kernel(const float* __restrict__ wg1,
                             const float* __restrict__ wg2,
                             const float* __restrict__ wq,
                             const float* __restrict__ wk,
                             const float* __restrict__ wv,
                             const float* __restrict__ wp,
                             const float* __restrict__ bp)
{
    const int t = threadIdx.x;
    if (blockIdx.x < 40) {
        const int e = blockIdx.x * 256 + t;
        const int lane = e & 31;
        const int kt   = (e >> 5) & 3;
        const int j    = (e >> 7) & 7;
        const int tau  = (e >> 10) & 1;
        const int wi   = e >> 11;
        const float* Wt[5] = { wg1, wg2, wq, wk, wv };
        const float* W = Wt[wi];
        const int n  = 8 * j + (lane >> 2);
        const int k0 = 16 * kt + 2 * (lane & 3);
        u32 h0, l0, h1, l1;
        bsplit2(W[k0 * 64 + n],       W[(k0 + 1) * 64 + n], h0, l0);
        bsplit2(W[(k0 + 8) * 64 + n], W[(k0 + 9) * 64 + n], h1, l1);
        uint2 r;
        r.x = tau ? l0 : h0;
        r.y = tau ? l1 : h1;
        g_bfrag[e] = r;
    } else if (t < 20) {
        if (t < 16) {
            const int a = t >> 2, b = t & 3;
            const float* ra = (a < 3) ? (wp + a * 64) : bp;
            const float* rb = (b < 3) ? (wp + b * 64) : bp;
            float s = 0.f;
            for (int c = 0; c < 64; c++) s += ra[c] * rb[c];
            g_gram[t] = s;
        } else {
            const int a = t - 16;
            const float* ra = (a < 3) ? (wp + a * 64) : bp;
            float s = 0.f;
            for (int c = 0; c < 64; c++) s += ra[c];
            g_gram[t] = s;
        }
    }
}

// ---------------------------------------------------------------------------
// Kernel A: q/k/v via mma.sync bf16-split. One warp per 16 feature rows.
// 128 threads = 4 warps = 64 rows/CTA. No SMEM, no block syncs.
// ---------------------------------------------------------------------------
__global__ __launch_bounds__(128, 4) void qkv_mma_kernel(
    const float* __restrict__ feat, int N,
    const float* __restrict__ bq, const float* __restrict__ bk,
    const float* __restrict__ bv)
{
    const int t = threadIdx.x;
    const int lane = t & 31;
    const int warp = t >> 5;
    const int base = 2 * (lane & 3);
    const int r1 = lane >> 2;

    const int row0 = (blockIdx.x * 4 + warp) * 16;
    const int rowA = row0 + r1;
    const int rowB = row0 + r1 + 8;
    const int rowAc = (rowA < N) ? rowA : N - 1;
    const int rowBc = (rowB < N) ? rowB : N - 1;

    // A fragments from feat (hi/lo split)
    u32 aHi[16], aLo[16];
#pragma unroll
    for (int m = 0; m < 8; m++) {
        const int c = 8 * m + base;
        const float2 fA = *(const float2*)(feat + rowAc * 64 + c);
        const float2 fB = *(const float2*)(feat + rowBc * 64 + c);
        const int kt = m >> 1;
        const int ro = (m & 1) << 1;
        bsplit2(fA.x, fA.y, aHi[kt * 4 + ro],     aLo[kt * 4 + ro]);
        bsplit2(fB.x, fB.y, aHi[kt * 4 + ro + 1], aLo[kt * 4 + ro + 1]);
    }

    const float* Bs[3] = { bq, bk, bv };
    float* Gs[3] = { g_q, g_k, g_v };
#pragma unroll 1
    for (int wi = 0; wi < 3; wi++) {
        const uint2* fr = g_bfrag + (2 + wi) * 2048;
        float d[8][4];
#pragma unroll
        for (int j = 0; j < 8; j++)
#pragma unroll
            for (int i = 0; i < 4; i++) d[j][i] = 0.f;
#pragma unroll
        for (int kt = 0; kt < 4; kt++) {
#pragma unroll
            for (int j = 0; j < 8; j++) {
                const uint2 bh = __ldg(&fr[j * 128 + kt * 32 + lane]);
                const uint2 bl = __ldg(&fr[1024 + j * 128 + kt * 32 + lane]);
                mma16816(d[j], &aHi[kt * 4], bh);
                mma16816(d[j], &aLo[kt * 4], bh);
                mma16816(d[j], &aHi[kt * 4], bl);
            }
        }
        float* G = Gs[wi];
        const float* B = Bs[wi];
#pragma unroll
        for (int j = 0; j < 8; j++) {
            const float2 b2 = __ldg((const float2*)(B + 8 * j + base));
            if (rowA < N)
                *(float2*)(G + rowA * 64 + 8 * j + base) =
                    make_float2(d[j][0] + b2.x, d[j][1] + b2.y);
            if (rowB < N)
                *(float2*)(G + rowB * 64 + 8 * j + base) =
                    make_float2(d[j][2] + b2.x, d[j][3] + b2.y);
        }
    }
}

// ---------------------------------------------------------------------------
// Kernel B: one warp per point, mma.sync bf16 split; gv in SMEM, occ=4 CTA/SM.
// ---------------------------------------------------------------------------
#define GVS 72   // smem row stride (floats) for gv tiles

__global__ __launch_bounds__(128, 4) void pt_mma_kernel(
    const float* __restrict__ points, const float* __restrict__ feat,
    const int* __restrict__ nbr, int N,
    const float* __restrict__ wp,  const float* __restrict__ wo,
    const float* __restrict__ bp,  const float* __restrict__ gp,
    const float* __restrict__ betap,
    const float* __restrict__ bg1, const float* __restrict__ gg,
    const float* __restrict__ betag,
    const float* __restrict__ bo,
    float* __restrict__ out)
{
    __shared__ float gvs[4 * 16 * GVS];
    __shared__ float mout[4][64];

    const int t = threadIdx.x;
    const int lane = t & 31;
    const int warp = t >> 5;

    int n = blockIdx.x * 4 + warp;
    if (n >= N) n = N - 1;

    const int base = 2 * (lane & 3);
    const int r1 = lane >> 2;
    float* mygv = gvs + warp * 16 * GVS;

    float M[20];
#pragma unroll
    for (int i = 0; i < 20; i++) M[i] = __ldg(&g_gram[i]);

    const int id1 = __ldg(&nbr[n * 16 + r1]);
    const int id2 = __ldg(&nbr[n * 16 + r1 + 8]);
    const float px = __ldg(&points[n * 3 + 0]);
    const float py = __ldg(&points[n * 3 + 1]);
    const float pz = __ldg(&points[n * 3 + 2]);
    const float rx1 = __ldg(&points[id1 * 3 + 0]) - px;
    const float ry1 = __ldg(&points[id1 * 3 + 1]) - py;
    const float rz1 = __ldg(&points[id1 * 3 + 2]) - pz;
    const float rx2 = __ldg(&points[id2 * 3 + 0]) - px;
    const float ry2 = __ldg(&points[id2 * 3 + 1]) - py;
    const float rz2 = __ldg(&points[id2 * 3 + 2]) - pz;

    float mean1, inv1, mean2, inv2;
    {
        const float s1 = fmaf(rx1, M[16], fmaf(ry1, M[17], fmaf(rz1, M[18], M[19])));
        const float tx = fmaf(rx1, M[0],  fmaf(ry1, M[1],  fmaf(rz1, M[2],  M[3])));
        const float ty = fmaf(rx1, M[4],  fmaf(ry1, M[5],  fmaf(rz1, M[6],  M[7])));
        const float tz = fmaf(rx1, M[8],  fmaf(ry1, M[9],  fmaf(rz1, M[10], M[11])));
        const float tw = fmaf(rx1, M[12], fmaf(ry1, M[13], fmaf(rz1, M[14], M[15])));
        const float s2 = fmaf(rx1, tx, fmaf(ry1, ty, fmaf(rz1, tz, tw)));
        mean1 = s1 * 0.015625f;
        inv1 = rsqrtf(s2 * 0.015625f - mean1 * mean1 + LN_EPS);
    }
    {
        const float s1 = fmaf(rx2, M[16], fmaf(ry2, M[17], fmaf(rz2, M[18], M[19])));
        const float tx = fmaf(rx2, M[0],  fmaf(ry2, M[1],  fmaf(rz2, M[2],  M[3])));
        const float ty = fmaf(rx2, M[4],  fmaf(ry2, M[5],  fmaf(rz2, M[6],  M[7])));
        const float tz = fmaf(rx2, M[8],  fmaf(ry2, M[9],  fmaf(rz2, M[10], M[11])));
        const float tw = fmaf(rx2, M[12], fmaf(ry2, M[13], fmaf(rz2, M[14], M[15])));
        const float s2 = fmaf(rx2, tx, fmaf(ry2, ty, fmaf(rz2, tz, tw)));
        mean2 = s1 * 0.015625f;
        inv2 = rsqrtf(s2 * 0.015625f - mean2 * mean2 + LN_EPS);
    }

    // ---- gather + positional LN/relu -> A fragments; gv+p -> SMEM ----
    u32 aHi[16], aLo[16];
#pragma unroll
    for (int m = 0; m < 8; m++) {
        const int c = 8 * m + base;
        const float2 q2 = *(const float2*)(g_q + n * 64 + c);
        const float2 k1 = *(const float2*)(g_k + id1 * 64 + c);
        const float2 k2 = *(const float2*)(g_k + id2 * 64 + c);
        const float2 v1 = *(const float2*)(g_v + id1 * 64 + c);
        const float2 v2 = *(const float2*)(g_v + id2 * 64 + c);
        const float2 wx = __ldg((const float2*)(wp + c));
        const float2 wy = __ldg((const float2*)(wp + 64 + c));
        const float2 wz = __ldg((const float2*)(wp + 128 + c));
        const float2 b2 = __ldg((const float2*)(bp + c));
        const float2 g2 = __ldg((const float2*)(gp + c));
        const float2 e2 = __ldg((const float2*)(betap + c));

        const float pA0 = fmaf(rx1, wx.x, fmaf(ry1, wy.x, fmaf(rz1, wz.x, b2.x)));
        const float pA1 = fmaf(rx1, wx.y, fmaf(ry1, wy.y, fmaf(rz1, wz.y, b2.y)));
        const float pB0 = fmaf(rx2, wx.x, fmaf(ry2, wy.x, fmaf(rz2, wz.x, b2.x)));
        const float pB1 = fmaf(rx2, wx.y, fmaf(ry2, wy.y, fmaf(rz2, wz.y, b2.y)));
        const float vA0 = fmaxf(fmaf((pA0 - mean1) * inv1, g2.x, e2.x), 0.f);
        const float vA1 = fmaxf(fmaf((pA1 - mean1) * inv1, g2.y, e2.y), 0.f);
        const float vB0 = fmaxf(fmaf((pB0 - mean2) * inv2, g2.x, e2.x), 0.f);
        const float vB1 = fmaxf(fmaf((pB1 - mean2) * inv2, g2.y, e2.y), 0.f);

        *(float2*)(mygv + r1 * GVS + c)       = make_float2(v1.x + vA0, v1.y + vA1);
        *(float2*)(mygv + (r1 + 8) * GVS + c) = make_float2(v2.x + vB0, v2.y + vB1);

        const int kt = m >> 1;
        const int ro = (m & 1) << 1;
        bsplit2(q2.x - k1.x + vA0, q2.y - k1.y + vA1,
                aHi[kt * 4 + ro], aLo[kt * 4 + ro]);
        bsplit2(q2.x - k2.x + vB0, q2.y - k2.y + vB1,
                aHi[kt * 4 + ro + 1], aLo[kt * 4 + ro + 1]);
    }

    // ---- GEMM1: d = attn @ wg1 ----
    float d[8][4];
#pragma unroll
    for (int j = 0; j < 8; j++)
#pragma unroll
        for (int i = 0; i < 4; i++) d[j][i] = 0.f;
#pragma unroll
    for (int kt = 0; kt < 4; kt++) {
#pragma unroll
        for (int j = 0; j < 8; j++) {
            const uint2 bh = __ldg(&g_bfrag[j * 128 + kt * 32 + lane]);
            const uint2 bl = __ldg(&g_bfrag[1024 + j * 128 + kt * 32 + lane]);
            mma16816(d[j], &aHi[kt * 4], bh);
            mma16816(d[j], &aLo[kt * 4], bh);
            mma16816(d[j], &aHi[kt * 4], bl);
        }
    }

    // ---- LN + relu over rows (4-lane groups) ----
    {
        float s1a = 0.f, s2a = 0.f, s1b = 0.f, s2b = 0.f;
#pragma unroll
        for (int j = 0; j < 8; j++) {
            const float2 bg = __ldg((const float2*)(bg1 + 8 * j + base));
            d[j][0] += bg.x; d[j][1] += bg.y;
            d[j][2] += bg.x; d[j][3] += bg.y;
            s1a += d[j][0] + d[j][1];
            s2a += d[j][0] * d[j][0] + d[j][1] * d[j][1];
            s1b += d[j][2] + d[j][3];
            s2b += d[j][2] * d[j][2] + d[j][3] * d[j][3];
        }
#pragma unroll
        for (int off = 1; off <= 2; off <<= 1) {
            s1a += __shfl_xor_sync(0xffffffffu, s1a, off);
            s2a += __shfl_xor_sync(0xffffffffu, s2a, off);
            s1b += __shfl_xor_sync(0xffffffffu, s1b, off);
            s2b += __shfl_xor_sync(0xffffffffu, s2b, off);
        }
        const float m1 = s1a * 0.015625f;
        const float i1 = rsqrtf(s2a * 0.015625f - m1 * m1 + LN_EPS);
        const float m2 = s1b * 0.015625f;
        const float i2 = rsqrtf(s2b * 0.015625f - m2 * m2 + LN_EPS);
#pragma unroll
        for (int j = 0; j < 8; j++) {
            const int c = 8 * j + base;
            const float2 gA = __ldg((const float2*)(gg + c));
            const float2 bA = __ldg((const float2*)(betag + c));
            d[j][0] = fmaxf(fmaf((d[j][0] - m1) * i1, gA.x, bA.x), 0.f);
            d[j][1] = fmaxf(fmaf((d[j][1] - m1) * i1, gA.y, bA.y), 0.f);
            d[j][2] = fmaxf(fmaf((d[j][2] - m2) * i2, gA.x, bA.x), 0.f);
            d[j][3] = fmaxf(fmaf((d[j][3] - m2) * i2, gA.y, bA.y), 0.f);
        }
    }

    // ---- repack h into A fragments (D layout == A layout) ----
#pragma unroll
    for (int kt = 0; kt < 4; kt++) {
        bsplit2(d[2 * kt][0],     d[2 * kt][1],     aHi[kt * 4 + 0], aLo[kt * 4 + 0]);
        bsplit2(d[2 * kt][2],     d[2 * kt][3],     aHi[kt * 4 + 1], aLo[kt * 4 + 1]);
        bsplit2(d[2 * kt + 1][0], d[2 * kt + 1][1], aHi[kt * 4 + 2], aLo[kt * 4 + 2]);
        bsplit2(d[2 * kt + 1][2], d[2 * kt + 1][3], aHi[kt * 4 + 3], aLo[kt * 4 + 3]);
    }

    // ---- GEMM2: w = h @ wg2 (bg2 cancels in softmax) ----
    float w[8][4];
#pragma unroll
    for (int j = 0; j < 8; j++)
#pragma unroll
        for (int i = 0; i < 4; i++) w[j][i] = 0.f;
#pragma unroll
    for (int kt = 0; kt < 4; kt++) {
#pragma unroll
        for (int j = 0; j < 8; j++) {
            const uint2 bh = __ldg(&g_bfrag[2048 + j * 128 + kt * 32 + lane]);
            const uint2 bl = __ldg(&g_bfrag[3072 + j * 128 + kt * 32 + lane]);
            mma16816(w[j], &aHi[kt * 4], bh);
            mma16816(w[j], &aLo[kt * 4], bh);
            mma16816(w[j], &aHi[kt * 4], bl);
        }
    }

    // ---- softmax over 16 neighbors ----
    {
        float mx0[8], mx1[8];
#pragma unroll
        for (int j = 0; j < 8; j++) {
            mx0[j] = fmaxf(w[j][0], w[j][2]);
            mx1[j] = fmaxf(w[j][1], w[j][3]);
        }
#pragma unroll
        for (int off = 4; off <= 16; off <<= 1)
#pragma unroll
            for (int j = 0; j < 8; j++) {
                mx0[j] = fmaxf(mx0[j], __shfl_xor_sync(0xffffffffu, mx0[j], off));
                mx1[j] = fmaxf(mx1[j], __shfl_xor_sync(0xffffffffu, mx1[j], off));
            }
        float s0[8], s1v[8], o0[8], o1[8];
#pragma unroll
        for (int j = 0; j < 8; j++) {
            const int c = 8 * j + base;
            const float2 gA = *(const float2*)(mygv + r1 * GVS + c);
            const float2 gB = *(const float2*)(mygv + (r1 + 8) * GVS + c);
            const float e00 = __expf(w[j][0] - mx0[j]);
            const float e20 = __expf(w[j][2] - mx0[j]);
            const float e11 = __expf(w[j][1] - mx1[j]);
            const float e31 = __expf(w[j][3] - mx1[j]);
            s0[j]  = e00 + e20;
            s1v[j] = e11 + e31;
            o0[j]  = e00 * gA.x + e20 * gB.x;
            o1[j]  = e11 * gA.y + e31 * gB.y;
        }
#pragma unroll
        for (int off = 4; off <= 16; off <<= 1)
#pragma unroll
            for (int j = 0; j < 8; j++) {
                s0[j]  += __shfl_xor_sync(0xffffffffu, s0[j], off);
                s1v[j] += __shfl_xor_sync(0xffffffffu, s1v[j], off);
                o0[j]  += __shfl_xor_sync(0xffffffffu, o0[j], off);
                o1[j]  += __shfl_xor_sync(0xffffffffu, o1[j], off);
            }
        if (lane < 4) {
#pragma unroll
            for (int j = 0; j < 8; j++) {
                mout[warp][8 * j + base]     = __fdividef(o0[j], s0[j]);
                mout[warp][8 * j + base + 1] = __fdividef(o1[j], s1v[j]);
            }
        }
    }
    __syncthreads();

    // ---- final: out = mout @ wo + bo + residual ----
    {
        const int p  = t >> 5;
        const int c2 = (t & 31) * 2;
        const int n3 = blockIdx.x * 4 + p;
        u64 acc = *(const u64*)(bo + c2);
        const float* mr = mout[p];
#pragma unroll 8
        for (int k = 0; k < 64; k++) {
            const u64 w2 = __ldg((const u64*)(wo + k * 64 + c2));
            fma2(acc, pack2f(mr[k]), w2);
        }
        if (n3 < N) {
            float r0, r1v;
            asm("mov.b64 {%0, %1}, %2;" : "=f"(r0), "=f"(r1v) : "l"(acc));
            const float2 f2 = *(const float2*)(feat + n3 * 64 + c2);
            *(float2*)(out + n3 * 64 + c2) = make_float2(r0 + f2.x, r1v + f2.y);
        }
    }
}

// ---------------------------------------------------------------------------
extern "C" void kernel_launch(void* const* d_in, const int* in_sizes, int n_in,
                              void* d_out, int out_size)
{
    const float* points = (const float*)d_in[0];
    const float* feat   = (const float*)d_in[1];
    const int*   nbr    = (const int*)  d_in[2];
    const float* wq     = (const float*)d_in[3];
    const float* bq     = (const float*)d_in[4];
    const float* wk     = (const float*)d_in[5];
    const float* bk     = (const float*)d_in[6];
    const float* wv     = (const float*)d_in[7];
    const float* bv     = (const float*)d_in[8];
    const float* wp     = (const float*)d_in[9];
    const float* bp     = (const float*)d_in[10];
    const float* gp     = (const float*)d_in[11];
    const float* betap  = (const float*)d_in[12];
    const float* wg1    = (const float*)d_in[13];
    const float* bg1    = (const float*)d_in[14];
    const float* gg     = (const float*)d_in[15];
    const float* betag  = (const float*)d_in[16];
    const float* wg2    = (const float*)d_in[17];
    const float* bg2    = (const float*)d_in[18];
    const float* wo     = (const float*)d_in[19];
    const float* bo     = (const float*)d_in[20];
    float* out = (float*)d_out;
    (void)bg2;   // cancels inside softmax

    const int N = in_sizes[0] / 3;

    build_kernel<<<41, 256>>>(wg1, wg2, wq, wk, wv, wp, bp);
    qkv_mma_kernel<<<(N + 63) / 64, 128>>>(feat, N, bq, bk, bv);
    pt_mma_kernel<<<(N + 3) / 4, 128>>>(points, feat, nbr, N,
                                        wp, wo, bp, gp, betap,
                                        bg1, gg, betag, bo, out);
}

// round 8
// speedup vs baseline: 2.2520x; 1.0557x over previous
#include <cuda_runtime.h>
#include <cuda_bf16.h>

#define NMAX 50176
#define LN_EPS 1e-5f

__device__ float g_q[NMAX * 64];
__device__ float g_k[NMAX * 64];
__device__ float g_v[NMAX * 64];

// B fragments: [weight(6: wg1,wg2,wq,wk,wv,wo)][term(2)][j(8)][kt(4)][lane(32)]
__device__ uint2 g_bfrag[12288];
__device__ float g_gram[20];

typedef unsigned long long u64;
typedef unsigned int u32;

__device__ __forceinline__ void bsplit2(float x, float y, u32& hp, u32& lp) {
    __nv_bfloat16 bx = __float2bfloat16_rn(x);
    __nv_bfloat16 by = __float2bfloat16_rn(y);
    float rx = x - __bfloat162float(bx);
    float ry = y - __bfloat162float(by);
    __nv_bfloat16 cx = __float2bfloat16_rn(rx);
    __nv_bfloat16 cy = __float2bfloat16_rn(ry);
    hp = (u32)__bfloat16_as_ushort(bx) | ((u32)__bfloat16_as_ushort(by) << 16);
    lp = (u32)__bfloat16_as_ushort(cx) | ((u32)__bfloat16_as_ushort(cy) << 16);
}
__device__ __forceinline__ void mma16816(float* d, const u32* a, uint2 b) {
    asm volatile(
        "mma.sync.aligned.m16n8k16.row.col.f32.bf16.bf16.f32 "
        "{%0,%1,%2,%3}, {%4,%5,%6,%7}, {%8,%9}, {%0,%1,%2,%3};"
        : "+f"(d[0]), "+f"(d[1]), "+f"(d[2]), "+f"(d[3])
        : "r"(a[0]), "r"(a[1]), "r"(a[2]), "r"(a[3]), "r"(b.x), "r"(b.y));
}

// ---------------------------------------------------------------------------
// Init: B fragments for 6 weights + Gram matrix. 49 CTAs.
// ---------------------------------------------------------------------------
__global__ void build_kernel(const float* __restrict__ wg1,
                             const float* __restrict__ wg2,
                             const float* __restrict__ wq,
                             const float* __restrict__ wk,
                             const float* __restrict__ wv,
                             const float* __restrict__ wo,
                             const float* __restrict__ wp,
                             const float* __restrict__ bp)
{
    const int t = threadIdx.x;
    if (blockIdx.x < 48) {
        const int e = blockIdx.x * 256 + t;
        const int lane = e & 31;
        const int kt   = (e >> 5) & 3;
        const int j    = (e >> 7) & 7;
        const int tau  = (e >> 10) & 1;
        const int wi   = e >> 11;
        const float* Wt[6] = { wg1, wg2, wq, wk, wv, wo };
        const float* W = Wt[wi];
        const int n  = 8 * j + (lane >> 2);
        const int k0 = 16 * kt + 2 * (lane & 3);
        u32 h0, l0, h1, l1;
        bsplit2(W[k0 * 64 + n],       W[(k0 + 1) * 64 + n], h0, l0);
        bsplit2(W[(k0 + 8) * 64 + n], W[(k0 + 9) * 64 + n], h1, l1);
        uint2 r;
        r.x = tau ? l0 : h0;
        r.y = tau ? l1 : h1;
        g_bfrag[e] = r;
    } else if (t < 20) {
        if (t < 16) {
            const int a = t >> 2, b = t & 3;
            const float* ra = (a < 3) ? (wp + a * 64) : bp;
            const float* rb = (b < 3) ? (wp + b * 64) : bp;
            float s = 0.f;
            for (int c = 0; c < 64; c++) s += ra[c] * rb[c];
            g_gram[t] = s;
        } else {
            const int a = t - 16;
            const float* ra = (a < 3) ? (wp + a * 64) : bp;
            float s = 0.f;
            for (int c = 0; c < 64; c++) s += ra[c];
            g_gram[t] = s;
        }
    }
}

// ---------------------------------------------------------------------------
// Kernel A: q/k/v via mma.sync bf16-split (unchanged — measured good)
// ---------------------------------------------------------------------------
__global__ __launch_bounds__(128, 4) void qkv_mma_kernel(
    const float* __restrict__ feat, int N,
    const float* __restrict__ bq, const float* __restrict__ bk,
    const float* __restrict__ bv)
{
    const int t = threadIdx.x;
    const int lane = t & 31;
    const int warp = t >> 5;
    const int base = 2 * (lane & 3);
    const int r1 = lane >> 2;

    const int row0 = (blockIdx.x * 4 + warp) * 16;
    const int rowA = row0 + r1;
    const int rowB = row0 + r1 + 8;
    const int rowAc = (rowA < N) ? rowA : N - 1;
    const int rowBc = (rowB < N) ? rowB : N - 1;

    u32 aHi[16], aLo[16];
#pragma unroll
    for (int m = 0; m < 8; m++) {
        const int c = 8 * m + base;
        const float2 fA = *(const float2*)(feat + rowAc * 64 + c);
        const float2 fB = *(const float2*)(feat + rowBc * 64 + c);
        const int kt = m >> 1;
        const int ro = (m & 1) << 1;
        bsplit2(fA.x, fA.y, aHi[kt * 4 + ro],     aLo[kt * 4 + ro]);
        bsplit2(fB.x, fB.y, aHi[kt * 4 + ro + 1], aLo[kt * 4 + ro + 1]);
    }

    const float* Bs[3] = { bq, bk, bv };
    float* Gs[3] = { g_q, g_k, g_v };
#pragma unroll 1
    for (int wi = 0; wi < 3; wi++) {
        const uint2* fr = g_bfrag + (2 + wi) * 2048;
        float d[8][4];
#pragma unroll
        for (int j = 0; j < 8; j++)
#pragma unroll
            for (int i = 0; i < 4; i++) d[j][i] = 0.f;
#pragma unroll
        for (int kt = 0; kt < 4; kt++) {
#pragma unroll
            for (int j = 0; j < 8; j++) {
                const uint2 bh = __ldg(&fr[j * 128 + kt * 32 + lane]);
                const uint2 bl = __ldg(&fr[1024 + j * 128 + kt * 32 + lane]);
                mma16816(d[j], &aHi[kt * 4], bh);
                mma16816(d[j], &aLo[kt * 4], bh);
                mma16816(d[j], &aHi[kt * 4], bl);
            }
        }
        float* G = Gs[wi];
        const float* B = Bs[wi];
#pragma unroll
        for (int j = 0; j < 8; j++) {
            const float2 b2 = __ldg((const float2*)(B + 8 * j + base));
            if (rowA < N)
                *(float2*)(G + rowA * 64 + 8 * j + base) =
                    make_float2(d[j][0] + b2.x, d[j][1] + b2.y);
            if (rowB < N)
                *(float2*)(G + rowB * 64 + 8 * j + base) =
                    make_float2(d[j][2] + b2.x, d[j][3] + b2.y);
        }
    }
}

// ---------------------------------------------------------------------------
// Kernel B: one warp per point; smem softmax; mma final GEMM.
// ---------------------------------------------------------------------------
#define GVS 72   // gv tile row stride
#define LWS 66   // logits / mout row stride

__global__ __launch_bounds__(128, 5) void pt_mma_kernel(
    const float* __restrict__ points, const float* __restrict__ feat,
    const int* __restrict__ nbr, int N,
    const float* __restrict__ wp,
    const float* __restrict__ bp,  const float* __restrict__ gp,
    const float* __restrict__ betap,
    const float* __restrict__ bg1, const float* __restrict__ gg,
    const float* __restrict__ betag,
    const float* __restrict__ bo,
    float* __restrict__ out)
{
    __shared__ float gvs[4 * 16 * GVS];     // 18432 B
    __shared__ float lw[4][16][LWS];        // 16896 B
    __shared__ float mout[16][LWS];         // 4224 B

    const int t = threadIdx.x;
    const int lane = t & 31;
    const int warp = t >> 5;

    // zero the unused final-A rows once
    for (int i = t; i < 12 * LWS; i += 128) mout[4][0 + 0] , mout[4 + i / LWS][i % LWS] = 0.f;
    __syncthreads();

    int n = blockIdx.x * 4 + warp;
    if (n >= N) n = N - 1;

    const int base = 2 * (lane & 3);
    const int r1 = lane >> 2;
    float* mygv = gvs + warp * 16 * GVS;

    float M[20];
#pragma unroll
    for (int i = 0; i < 20; i++) M[i] = __ldg(&g_gram[i]);

    const int id1 = __ldg(&nbr[n * 16 + r1]);
    const int id2 = __ldg(&nbr[n * 16 + r1 + 8]);
    const float px = __ldg(&points[n * 3 + 0]);
    const float py = __ldg(&points[n * 3 + 1]);
    const float pz = __ldg(&points[n * 3 + 2]);
    const float rx1 = __ldg(&points[id1 * 3 + 0]) - px;
    const float ry1 = __ldg(&points[id1 * 3 + 1]) - py;
    const float rz1 = __ldg(&points[id1 * 3 + 2]) - pz;
    const float rx2 = __ldg(&points[id2 * 3 + 0]) - px;
    const float ry2 = __ldg(&points[id2 * 3 + 1]) - py;
    const float rz2 = __ldg(&points[id2 * 3 + 2]) - pz;

    float mean1, inv1, mean2, inv2;
    {
        const float s1 = fmaf(rx1, M[16], fmaf(ry1, M[17], fmaf(rz1, M[18], M[19])));
        const float tx = fmaf(rx1, M[0],  fmaf(ry1, M[1],  fmaf(rz1, M[2],  M[3])));
        const float ty = fmaf(rx1, M[4],  fmaf(ry1, M[5],  fmaf(rz1, M[6],  M[7])));
        const float tz = fmaf(rx1, M[8],  fmaf(ry1, M[9],  fmaf(rz1, M[10], M[11])));
        const float tw = fmaf(rx1, M[12], fmaf(ry1, M[13], fmaf(rz1, M[14], M[15])));
        const float s2 = fmaf(rx1, tx, fmaf(ry1, ty, fmaf(rz1, tz, tw)));
        mean1 = s1 * 0.015625f;
        inv1 = rsqrtf(s2 * 0.015625f - mean1 * mean1 + LN_EPS);
    }
    {
        const float s1 = fmaf(rx2, M[16], fmaf(ry2, M[17], fmaf(rz2, M[18], M[19])));
        const float tx = fmaf(rx2, M[0],  fmaf(ry2, M[1],  fmaf(rz2, M[2],  M[3])));
        const float ty = fmaf(rx2, M[4],  fmaf(ry2, M[5],  fmaf(rz2, M[6],  M[7])));
        const float tz = fmaf(rx2, M[8],  fmaf(ry2, M[9],  fmaf(rz2, M[10], M[11])));
        const float tw = fmaf(rx2, M[12], fmaf(ry2, M[13], fmaf(rz2, M[14], M[15])));
        const float s2 = fmaf(rx2, tx, fmaf(ry2, ty, fmaf(rz2, tz, tw)));
        mean2 = s1 * 0.015625f;
        inv2 = rsqrtf(s2 * 0.015625f - mean2 * mean2 + LN_EPS);
    }

    // ---- gather + positional LN/relu -> A fragments; gv+p -> SMEM ----
    u32 aHi[16], aLo[16];
#pragma unroll
    for (int m = 0; m < 8; m++) {
        const int c = 8 * m + base;
        const float2 q2 = *(const float2*)(g_q + n * 64 + c);
        const float2 k1 = *(const float2*)(g_k + id1 * 64 + c);
        const float2 k2 = *(const float2*)(g_k + id2 * 64 + c);
        const float2 v1 = *(const float2*)(g_v + id1 * 64 + c);
        const float2 v2 = *(const float2*)(g_v + id2 * 64 + c);
        const float2 wx = __ldg((const float2*)(wp + c));
        const float2 wy = __ldg((const float2*)(wp + 64 + c));
        const float2 wz = __ldg((const float2*)(wp + 128 + c));
        const float2 b2 = __ldg((const float2*)(bp + c));
        const float2 g2 = __ldg((const float2*)(gp + c));
        const float2 e2 = __ldg((const float2*)(betap + c));

        const float pA0 = fmaf(rx1, wx.x, fmaf(ry1, wy.x, fmaf(rz1, wz.x, b2.x)));
        const float pA1 = fmaf(rx1, wx.y, fmaf(ry1, wy.y, fmaf(rz1, wz.y, b2.y)));
        const float pB0 = fmaf(rx2, wx.x, fmaf(ry2, wy.x, fmaf(rz2, wz.x, b2.x)));
        const float pB1 = fmaf(rx2, wx.y, fmaf(ry2, wy.y, fmaf(rz2, wz.y, b2.y)));
        const float vA0 = fmaxf(fmaf((pA0 - mean1) * inv1, g2.x, e2.x), 0.f);
        const float vA1 = fmaxf(fmaf((pA1 - mean1) * inv1, g2.y, e2.y), 0.f);
        const float vB0 = fmaxf(fmaf((pB0 - mean2) * inv2, g2.x, e2.x), 0.f);
        const float vB1 = fmaxf(fmaf((pB1 - mean2) * inv2, g2.y, e2.y), 0.f);

        *(float2*)(mygv + r1 * GVS + c)       = make_float2(v1.x + vA0, v1.y + vA1);
        *(float2*)(mygv + (r1 + 8) * GVS + c) = make_float2(v2.x + vB0, v2.y + vB1);

        const int kt = m >> 1;
        const int ro = (m & 1) << 1;
        bsplit2(q2.x - k1.x + vA0, q2.y - k1.y + vA1,
                aHi[kt * 4 + ro], aLo[kt * 4 + ro]);
        bsplit2(q2.x - k2.x + vB0, q2.y - k2.y + vB1,
                aHi[kt * 4 + ro + 1], aLo[kt * 4 + ro + 1]);
    }

    // ---- GEMM1: d = attn @ wg1 ----
    float d[8][4];
#pragma unroll
    for (int j = 0; j < 8; j++)
#pragma unroll
        for (int i = 0; i < 4; i++) d[j][i] = 0.f;
#pragma unroll
    for (int kt = 0; kt < 4; kt++) {
#pragma unroll
        for (int j = 0; j < 8; j++) {
            const uint2 bh = __ldg(&g_bfrag[j * 128 + kt * 32 + lane]);
            const uint2 bl = __ldg(&g_bfrag[1024 + j * 128 + kt * 32 + lane]);
            mma16816(d[j], &aHi[kt * 4], bh);
            mma16816(d[j], &aLo[kt * 4], bh);
            mma16816(d[j], &aHi[kt * 4], bl);
        }
    }

    // ---- LN + relu over rows (4-lane groups) ----
    {
        float s1a = 0.f, s2a = 0.f, s1b = 0.f, s2b = 0.f;
#pragma unroll
        for (int j = 0; j < 8; j++) {
            const float2 bg = __ldg((const float2*)(bg1 + 8 * j + base));
            d[j][0] += bg.x; d[j][1] += bg.y;
            d[j][2] += bg.x; d[j][3] += bg.y;
            s1a += d[j][0] + d[j][1];
            s2a += d[j][0] * d[j][0] + d[j][1] * d[j][1];
            s1b += d[j][2] + d[j][3];
            s2b += d[j][2] * d[j][2] + d[j][3] * d[j][3];
        }
#pragma unroll
        for (int off = 1; off <= 2; off <<= 1) {
            s1a += __shfl_xor_sync(0xffffffffu, s1a, off);
            s2a += __shfl_xor_sync(0xffffffffu, s2a, off);
            s1b += __shfl_xor_sync(0xffffffffu, s1b, off);
            s2b += __shfl_xor_sync(0xffffffffu, s2b, off);
        }
        const float m1 = s1a * 0.015625f;
        const float i1 = rsqrtf(s2a * 0.015625f - m1 * m1 + LN_EPS);
        const float m2 = s1b * 0.015625f;
        const float i2 = rsqrtf(s2b * 0.015625f - m2 * m2 + LN_EPS);
#pragma unroll
        for (int j = 0; j < 8; j++) {
            const int c = 8 * j + base;
            const float2 gA = __ldg((const float2*)(gg + c));
            const float2 bA = __ldg((const float2*)(betag + c));
            d[j][0] = fmaxf(fmaf((d[j][0] - m1) * i1, gA.x, bA.x), 0.f);
            d[j][1] = fmaxf(fmaf((d[j][1] - m1) * i1, gA.y, bA.y), 0.f);
            d[j][2] = fmaxf(fmaf((d[j][2] - m2) * i2, gA.x, bA.x), 0.f);
            d[j][3] = fmaxf(fmaf((d[j][3] - m2) * i2, gA.y, bA.y), 0.f);
        }
    }

    // ---- repack h into A fragments ----
#pragma unroll
    for (int kt = 0; kt < 4; kt++) {
        bsplit2(d[2 * kt][0],     d[2 * kt][1],     aHi[kt * 4 + 0], aLo[kt * 4 + 0]);
        bsplit2(d[2 * kt][2],     d[2 * kt][3],     aHi[kt * 4 + 1], aLo[kt * 4 + 1]);
        bsplit2(d[2 * kt + 1][0], d[2 * kt + 1][1], aHi[kt * 4 + 2], aLo[kt * 4 + 2]);
        bsplit2(d[2 * kt + 1][2], d[2 * kt + 1][3], aHi[kt * 4 + 3], aLo[kt * 4 + 3]);
    }

    // ---- GEMM2: logits = h @ wg2 (bg2 cancels in softmax) ----
#pragma unroll
    for (int j = 0; j < 8; j++)
#pragma unroll
        for (int i = 0; i < 4; i++) d[j][i] = 0.f;
#pragma unroll
    for (int kt = 0; kt < 4; kt++) {
#pragma unroll
        for (int j = 0; j < 8; j++) {
            const uint2 bh = __ldg(&g_bfrag[2048 + j * 128 + kt * 32 + lane]);
            const uint2 bl = __ldg(&g_bfrag[3072 + j * 128 + kt * 32 + lane]);
            mma16816(d[j], &aHi[kt * 4], bh);
            mma16816(d[j], &aLo[kt * 4], bh);
            mma16816(d[j], &aHi[kt * 4], bl);
        }
    }

    // ---- stage logits to smem; column softmax ----
#pragma unroll
    for (int j = 0; j < 8; j++) {
        *(float2*)&lw[warp][r1][8 * j + base]     = make_float2(d[j][0], d[j][1]);
        *(float2*)&lw[warp][r1 + 8][8 * j + base] = make_float2(d[j][2], d[j][3]);
    }
    __syncwarp();
#pragma unroll
    for (int cc = 0; cc < 2; cc++) {
        const int c = lane + 32 * cc;
        float mx = -3.4e38f;
#pragma unroll
        for (int k = 0; k < 16; k++) mx = fmaxf(mx, lw[warp][k][c]);
        float s = 0.f, o = 0.f;
#pragma unroll
        for (int k = 0; k < 16; k++) {
            const float e = __expf(lw[warp][k][c] - mx);
            s += e;
            o = fmaf(e, mygv[k * GVS + c], o);
        }
        mout[warp][c] = __fdividef(o, s);
    }
    __syncthreads();

    // ---- final GEMM via mma: out = mout @ wo + bo + residual ----
    {
        u32 aH2[16], aL2[16];
#pragma unroll
        for (int m = 0; m < 8; m++) {
            const int c = 8 * m + base;
            const float2 fA = *(const float2*)&mout[r1][c];
            const float2 fB = *(const float2*)&mout[r1 + 8][c];
            const int kt = m >> 1;
            const int ro = (m & 1) << 1;
            bsplit2(fA.x, fA.y, aH2[kt * 4 + ro],     aL2[kt * 4 + ro]);
            bsplit2(fB.x, fB.y, aH2[kt * 4 + ro + 1], aL2[kt * 4 + ro + 1]);
        }
        float dd[2][4];
#pragma unroll
        for (int jj = 0; jj < 2; jj++)
#pragma unroll
            for (int i = 0; i < 4; i++) dd[jj][i] = 0.f;
#pragma unroll
        for (int kt = 0; kt < 4; kt++) {
#pragma unroll
            for (int jj = 0; jj < 2; jj++) {
                const int j = 2 * warp + jj;
                const uint2 bh = __ldg(&g_bfrag[10240 + j * 128 + kt * 32 + lane]);
                const uint2 bl = __ldg(&g_bfrag[11264 + j * 128 + kt * 32 + lane]);
                mma16816(dd[jj], &aH2[kt * 4], bh);
                mma16816(dd[jj], &aL2[kt * 4], bh);
                mma16816(dd[jj], &aH2[kt * 4], bl);
            }
        }
        if (r1 < 4) {
            const int n3 = blockIdx.x * 4 + r1;
            if (n3 < N) {
#pragma unroll
                for (int jj = 0; jj < 2; jj++) {
                    const int c = 8 * (2 * warp + jj) + base;
                    const float2 b2 = __ldg((const float2*)(bo + c));
                    const float2 f2 = *(const float2*)(feat + n3 * 64 + c);
                    *(float2*)(out + n3 * 64 + c) =
                        make_float2(dd[jj][0] + b2.x + f2.x,
                                    dd[jj][1] + b2.y + f2.y);
                }
            }
        }
    }
}

// ---------------------------------------------------------------------------
extern "C" void kernel_launch(void* const* d_in, const int* in_sizes, int n_in,
                              void* d_out, int out_size)
{
    const float* points = (const float*)d_in[0];
    const float* feat   = (const float*)d_in[1];
    const int*   nbr    = (const int*)  d_in[2];
    const float* wq     = (const float*)d_in[3];
    const float* bq     = (const float*)d_in[4];
    const float* wk     = (const float*)d_in[5];
    const float* bk     = (const float*)d_in[6];
    const float* wv     = (const float*)d_in[7];
    const float* bv     = (const float*)d_in[8];
    const float* wp     = (const float*)d_in[9];
    const float* bp     = (const float*)d_in[10];
    const float* gp     = (const float*)d_in[11];
    const float* betap  = (const float*)d_in[12];
    const float* wg1    = (const float*)d_in[13];
    const float* bg1    = (const float*)d_in[14];
    const float* gg     = (const float*)d_in[15];
    const float* betag  = (const float*)d_in[16];
    const float* wg2    = (const float*)d_in[17];
    const float* bg2    = (const float*)d_in[18];
    const float* wo     = (const float*)d_in[19];
    const float* bo     = (const float*)d_in[20];
    float* out = (float*)d_out;
    (void)bg2;

    const int N = in_sizes[0] / 3;

    build_kernel<<<49, 256>>>(wg1, wg2, wq, wk, wv, wo, wp, bp);
    qkv_mma_kernel<<<(N + 63) / 64, 128>>>(feat, N, bq, bk, bv);
    pt_mma_kernel<<<(N + 3) / 4, 128>>>(points, feat, nbr, N,
                                        wp, bp, gp, betap,
                                        bg1, gg, betag, bo, out);
}

// round 9
// speedup vs baseline: 2.2853x; 1.0148x over previous
#include <cuda_runtime.h>
#include <cuda_bf16.h>

#define NMAX 50176
#define LN_EPS 1e-5f

__device__ float g_q[NMAX * 64];
__device__ float g_k[NMAX * 64];
__device__ float g_v[NMAX * 64];

// B fragments: [weight(6: wg1,wg2,wq,wk,wv,wo)][term(2)][j(8)][kt(4)][lane(32)]
__device__ uint2 g_bfrag[12288];
__device__ float g_gram[20];

typedef unsigned long long u64;
typedef unsigned int u32;

// pack bf16(hi)<<16 | bf16(lo) in one cvt
__device__ __forceinline__ u32 cvt2bf(float hi, float lo) {
    u32 r;
    asm("cvt.rn.bf16x2.f32 %0, %1, %2;" : "=r"(r) : "f"(hi), "f"(lo));
    return r;
}
// split (x,y) into packed bf16x2 hi and lo parts (x in low half)
__device__ __forceinline__ void bsplit2(float x, float y, u32& hp, u32& lp) {
    hp = cvt2bf(y, x);
    const float hx = __uint_as_float(hp << 16);
    const float hy = __uint_as_float(hp & 0xFFFF0000u);
    lp = cvt2bf(y - hy, x - hx);
}
__device__ __forceinline__ void mma16816(float* d, const u32* a, uint2 b) {
    asm volatile(
        "mma.sync.aligned.m16n8k16.row.col.f32.bf16.bf16.f32 "
        "{%0,%1,%2,%3}, {%4,%5,%6,%7}, {%8,%9}, {%0,%1,%2,%3};"
        : "+f"(d[0]), "+f"(d[1]), "+f"(d[2]), "+f"(d[3])
        : "r"(a[0]), "r"(a[1]), "r"(a[2]), "r"(a[3]), "r"(b.x), "r"(b.y));
}

// ---------------------------------------------------------------------------
// Init: B fragments for 6 weights + Gram matrix. 49 CTAs.
// ---------------------------------------------------------------------------
__global__ void build_kernel(const float* __restrict__ wg1,
                             const float* __restrict__ wg2,
                             const float* __restrict__ wq,
                             const float* __restrict__ wk,
                             const float* __restrict__ wv,
                             const float* __restrict__ wo,
                             const float* __restrict__ wp,
                             const float* __restrict__ bp)
{
    const int t = threadIdx.x;
    if (blockIdx.x < 48) {
        const int e = blockIdx.x * 256 + t;
        const int lane = e & 31;
        const int kt   = (e >> 5) & 3;
        const int j    = (e >> 7) & 7;
        const int tau  = (e >> 10) & 1;
        const int wi   = e >> 11;
        const float* Wt[6] = { wg1, wg2, wq, wk, wv, wo };
        const float* W = Wt[wi];
        const int n  = 8 * j + (lane >> 2);
        const int k0 = 16 * kt + 2 * (lane & 3);
        u32 h0, l0, h1, l1;
        bsplit2(W[k0 * 64 + n],       W[(k0 + 1) * 64 + n], h0, l0);
        bsplit2(W[(k0 + 8) * 64 + n], W[(k0 + 9) * 64 + n], h1, l1);
        uint2 r;
        r.x = tau ? l0 : h0;
        r.y = tau ? l1 : h1;
        g_bfrag[e] = r;
    } else if (t < 20) {
        if (t < 16) {
            const int a = t >> 2, b = t & 3;
            const float* ra = (a < 3) ? (wp + a * 64) : bp;
            const float* rb = (b < 3) ? (wp + b * 64) : bp;
            float s = 0.f;
            for (int c = 0; c < 64; c++) s += ra[c] * rb[c];
            g_gram[t] = s;
        } else {
            const int a = t - 16;
            const float* ra = (a < 3) ? (wp + a * 64) : bp;
            float s = 0.f;
            for (int c = 0; c < 64; c++) s += ra[c];
            g_gram[t] = s;
        }
    }
}

// ---------------------------------------------------------------------------
// Kernel A: q/k/v via mma.sync bf16-split.
// ---------------------------------------------------------------------------
__global__ __launch_bounds__(128, 4) void qkv_mma_kernel(
    const float* __restrict__ feat, int N,
    const float* __restrict__ bq, const float* __restrict__ bk,
    const float* __restrict__ bv)
{
    const int t = threadIdx.x;
    const int lane = t & 31;
    const int warp = t >> 5;
    const int base = 2 * (lane & 3);
    const int r1 = lane >> 2;

    const int row0 = (blockIdx.x * 4 + warp) * 16;
    const int rowA = row0 + r1;
    const int rowB = row0 + r1 + 8;
    const int rowAc = (rowA < N) ? rowA : N - 1;
    const int rowBc = (rowB < N) ? rowB : N - 1;

    u32 aHi[16], aLo[16];
#pragma unroll
    for (int m = 0; m < 8; m++) {
        const int c = 8 * m + base;
        const float2 fA = *(const float2*)(feat + rowAc * 64 + c);
        const float2 fB = *(const float2*)(feat + rowBc * 64 + c);
        const int kt = m >> 1;
        const int ro = (m & 1) << 1;
        bsplit2(fA.x, fA.y, aHi[kt * 4 + ro],     aLo[kt * 4 + ro]);
        bsplit2(fB.x, fB.y, aHi[kt * 4 + ro + 1], aLo[kt * 4 + ro + 1]);
    }

    const float* Bs[3] = { bq, bk, bv };
    float* Gs[3] = { g_q, g_k, g_v };
#pragma unroll 1
    for (int wi = 0; wi < 3; wi++) {
        const uint2* fr = g_bfrag + (2 + wi) * 2048;
        float d[8][4];
#pragma unroll
        for (int j = 0; j < 8; j++)
#pragma unroll
            for (int i = 0; i < 4; i++) d[j][i] = 0.f;
#pragma unroll
        for (int kt = 0; kt < 4; kt++) {
#pragma unroll
            for (int j = 0; j < 8; j++) {
                const uint2 bh = __ldg(&fr[j * 128 + kt * 32 + lane]);
                const uint2 bl = __ldg(&fr[1024 + j * 128 + kt * 32 + lane]);
                mma16816(d[j], &aHi[kt * 4], bh);
                mma16816(d[j], &aLo[kt * 4], bh);
                mma16816(d[j], &aHi[kt * 4], bl);
            }
        }
        float* G = Gs[wi];
        const float* B = Bs[wi];
#pragma unroll
        for (int j = 0; j < 8; j++) {
            const float2 b2 = __ldg((const float2*)(B + 8 * j + base));
            if (rowA < N)
                *(float2*)(G + rowA * 64 + 8 * j + base) =
                    make_float2(d[j][0] + b2.x, d[j][1] + b2.y);
            if (rowB < N)
                *(float2*)(G + rowB * 64 + 8 * j + base) =
                    make_float2(d[j][2] + b2.x, d[j][3] + b2.y);
        }
    }
}

// ---------------------------------------------------------------------------
// Kernel B: one warp per point; smem softmax; mma final GEMM. 6 CTA/SM.
// ---------------------------------------------------------------------------
#define GVS 66   // gv tile row stride
#define LWS 66   // logits row stride

__global__ __launch_bounds__(128, 6) void pt_mma_kernel(
    const float* __restrict__ points, const float* __restrict__ feat,
    const int* __restrict__ nbr, int N,
    const float* __restrict__ wp,
    const float* __restrict__ bp,  const float* __restrict__ gp,
    const float* __restrict__ betap,
    const float* __restrict__ bg1, const float* __restrict__ gg,
    const float* __restrict__ betag,
    const float* __restrict__ bo,
    float* __restrict__ out)
{
    __shared__ float gvs[4 * 16 * GVS];   // 16896 B
    __shared__ float lw[4][16][LWS];      // 16896 B
    __shared__ float mout[4][LWS];        // 1056 B

    const int t = threadIdx.x;
    const int lane = t & 31;
    const int warp = t >> 5;

    int n = blockIdx.x * 4 + warp;
    if (n >= N) n = N - 1;

    const int base = 2 * (lane & 3);
    const int r1 = lane >> 2;
    float* mygv = gvs + warp * 16 * GVS;

    float M[20];
#pragma unroll
    for (int i = 0; i < 20; i++) M[i] = __ldg(&g_gram[i]);

    const int id1 = __ldg(&nbr[n * 16 + r1]);
    const int id2 = __ldg(&nbr[n * 16 + r1 + 8]);
    const float px = __ldg(&points[n * 3 + 0]);
    const float py = __ldg(&points[n * 3 + 1]);
    const float pz = __ldg(&points[n * 3 + 2]);
    const float rx1 = __ldg(&points[id1 * 3 + 0]) - px;
    const float ry1 = __ldg(&points[id1 * 3 + 1]) - py;
    const float rz1 = __ldg(&points[id1 * 3 + 2]) - pz;
    const float rx2 = __ldg(&points[id2 * 3 + 0]) - px;
    const float ry2 = __ldg(&points[id2 * 3 + 1]) - py;
    const float rz2 = __ldg(&points[id2 * 3 + 2]) - pz;

    float mean1, inv1, mean2, inv2;
    {
        const float s1 = fmaf(rx1, M[16], fmaf(ry1, M[17], fmaf(rz1, M[18], M[19])));
        const float tx = fmaf(rx1, M[0],  fmaf(ry1, M[1],  fmaf(rz1, M[2],  M[3])));
        const float ty = fmaf(rx1, M[4],  fmaf(ry1, M[5],  fmaf(rz1, M[6],  M[7])));
        const float tz = fmaf(rx1, M[8],  fmaf(ry1, M[9],  fmaf(rz1, M[10], M[11])));
        const float tw = fmaf(rx1, M[12], fmaf(ry1, M[13], fmaf(rz1, M[14], M[15])));
        const float s2 = fmaf(rx1, tx, fmaf(ry1, ty, fmaf(rz1, tz, tw)));
        mean1 = s1 * 0.015625f;
        inv1 = rsqrtf(s2 * 0.015625f - mean1 * mean1 + LN_EPS);
    }
    {
        const float s1 = fmaf(rx2, M[16], fmaf(ry2, M[17], fmaf(rz2, M[18], M[19])));
        const float tx = fmaf(rx2, M[0],  fmaf(ry2, M[1],  fmaf(rz2, M[2],  M[3])));
        const float ty = fmaf(rx2, M[4],  fmaf(ry2, M[5],  fmaf(rz2, M[6],  M[7])));
        const float tz = fmaf(rx2, M[8],  fmaf(ry2, M[9],  fmaf(rz2, M[10], M[11])));
        const float tw = fmaf(rx2, M[12], fmaf(ry2, M[13], fmaf(rz2, M[14], M[15])));
        const float s2 = fmaf(rx2, tx, fmaf(ry2, ty, fmaf(rz2, tz, tw)));
        mean2 = s1 * 0.015625f;
        inv2 = rsqrtf(s2 * 0.015625f - mean2 * mean2 + LN_EPS);
    }

    // ---- gather + positional LN/relu -> A fragments; gv+p -> SMEM ----
    u32 aHi[16], aLo[16];
#pragma unroll
    for (int m = 0; m < 8; m++) {
        const int c = 8 * m + base;
        const float2 q2 = *(const float2*)(g_q + n * 64 + c);
        const float2 k1 = *(const float2*)(g_k + id1 * 64 + c);
        const float2 k2 = *(const float2*)(g_k + id2 * 64 + c);
        const float2 v1 = *(const float2*)(g_v + id1 * 64 + c);
        const float2 v2 = *(const float2*)(g_v + id2 * 64 + c);
        const float2 wx = __ldg((const float2*)(wp + c));
        const float2 wy = __ldg((const float2*)(wp + 64 + c));
        const float2 wz = __ldg((const float2*)(wp + 128 + c));
        const float2 b2 = __ldg((const float2*)(bp + c));
        const float2 g2 = __ldg((const float2*)(gp + c));
        const float2 e2 = __ldg((const float2*)(betap + c));

        const float pA0 = fmaf(rx1, wx.x, fmaf(ry1, wy.x, fmaf(rz1, wz.x, b2.x)));
        const float pA1 = fmaf(rx1, wx.y, fmaf(ry1, wy.y, fmaf(rz1, wz.y, b2.y)));
        const float pB0 = fmaf(rx2, wx.x, fmaf(ry2, wy.x, fmaf(rz2, wz.x, b2.x)));
        const float pB1 = fmaf(rx2, wx.y, fmaf(ry2, wy.y, fmaf(rz2, wz.y, b2.y)));
        const float vA0 = fmaxf(fmaf((pA0 - mean1) * inv1, g2.x, e2.x), 0.f);
        const float vA1 = fmaxf(fmaf((pA1 - mean1) * inv1, g2.y, e2.y), 0.f);
        const float vB0 = fmaxf(fmaf((pB0 - mean2) * inv2, g2.x, e2.x), 0.f);
        const float vB1 = fmaxf(fmaf((pB1 - mean2) * inv2, g2.y, e2.y), 0.f);

        *(float2*)(mygv + r1 * GVS + c)       = make_float2(v1.x + vA0, v1.y + vA1);
        *(float2*)(mygv + (r1 + 8) * GVS + c) = make_float2(v2.x + vB0, v2.y + vB1);

        const int kt = m >> 1;
        const int ro = (m & 1) << 1;
        bsplit2(q2.x - k1.x + vA0, q2.y - k1.y + vA1,
                aHi[kt * 4 + ro], aLo[kt * 4 + ro]);
        bsplit2(q2.x - k2.x + vB0, q2.y - k2.y + vB1,
                aHi[kt * 4 + ro + 1], aLo[kt * 4 + ro + 1]);
    }

    // ---- GEMM1: d = attn @ wg1 ----
    float d[8][4];
#pragma unroll
    for (int j = 0; j < 8; j++)
#pragma unroll
        for (int i = 0; i < 4; i++) d[j][i] = 0.f;
#pragma unroll
    for (int kt = 0; kt < 4; kt++) {
#pragma unroll
        for (int j = 0; j < 8; j++) {
            const uint2 bh = __ldg(&g_bfrag[j * 128 + kt * 32 + lane]);
            const uint2 bl = __ldg(&g_bfrag[1024 + j * 128 + kt * 32 + lane]);
            mma16816(d[j], &aHi[kt * 4], bh);
            mma16816(d[j], &aLo[kt * 4], bh);
            mma16816(d[j], &aHi[kt * 4], bl);
        }
    }

    // ---- LN + relu over rows (4-lane groups) ----
    {
        float s1a = 0.f, s2a = 0.f, s1b = 0.f, s2b = 0.f;
#pragma unroll
        for (int j = 0; j < 8; j++) {
            const float2 bg = __ldg((const float2*)(bg1 + 8 * j + base));
            d[j][0] += bg.x; d[j][1] += bg.y;
            d[j][2] += bg.x; d[j][3] += bg.y;
            s1a += d[j][0] + d[j][1];
            s2a += d[j][0] * d[j][0] + d[j][1] * d[j][1];
            s1b += d[j][2] + d[j][3];
            s2b += d[j][2] * d[j][2] + d[j][3] * d[j][3];
        }
#pragma unroll
        for (int off = 1; off <= 2; off <<= 1) {
            s1a += __shfl_xor_sync(0xffffffffu, s1a, off);
            s2a += __shfl_xor_sync(0xffffffffu, s2a, off);
            s1b += __shfl_xor_sync(0xffffffffu, s1b, off);
            s2b += __shfl_xor_sync(0xffffffffu, s2b, off);
        }
        const float m1 = s1a * 0.015625f;
        const float i1 = rsqrtf(s2a * 0.015625f - m1 * m1 + LN_EPS);
        const float m2 = s1b * 0.015625f;
        const float i2 = rsqrtf(s2b * 0.015625f - m2 * m2 + LN_EPS);
#pragma unroll
        for (int j = 0; j < 8; j++) {
            const int c = 8 * j + base;
            const float2 gA = __ldg((const float2*)(gg + c));
            const float2 bA = __ldg((const float2*)(betag + c));
            d[j][0] = fmaxf(fmaf((d[j][0] - m1) * i1, gA.x, bA.x), 0.f);
            d[j][1] = fmaxf(fmaf((d[j][1] - m1) * i1, gA.y, bA.y), 0.f);
            d[j][2] = fmaxf(fmaf((d[j][2] - m2) * i2, gA.x, bA.x), 0.f);
            d[j][3] = fmaxf(fmaf((d[j][3] - m2) * i2, gA.y, bA.y), 0.f);
        }
    }

    // ---- repack h into A fragments ----
#pragma unroll
    for (int kt = 0; kt < 4; kt++) {
        bsplit2(d[2 * kt][0],     d[2 * kt][1],     aHi[kt * 4 + 0], aLo[kt * 4 + 0]);
        bsplit2(d[2 * kt][2],     d[2 * kt][3],     aHi[kt * 4 + 1], aLo[kt * 4 + 1]);
        bsplit2(d[2 * kt + 1][0], d[2 * kt + 1][1], aHi[kt * 4 + 2], aLo[kt * 4 + 2]);
        bsplit2(d[2 * kt + 1][2], d[2 * kt + 1][3], aHi[kt * 4 + 3], aLo[kt * 4 + 3]);
    }

    // ---- GEMM2: logits = h @ wg2 (bg2 cancels in softmax) ----
#pragma unroll
    for (int j = 0; j < 8; j++)
#pragma unroll
        for (int i = 0; i < 4; i++) d[j][i] = 0.f;
#pragma unroll
    for (int kt = 0; kt < 4; kt++) {
#pragma unroll
        for (int j = 0; j < 8; j++) {
            const uint2 bh = __ldg(&g_bfrag[2048 + j * 128 + kt * 32 + lane]);
            const uint2 bl = __ldg(&g_bfrag[3072 + j * 128 + kt * 32 + lane]);
            mma16816(d[j], &aHi[kt * 4], bh);
            mma16816(d[j], &aLo[kt * 4], bh);
            mma16816(d[j], &aHi[kt * 4], bl);
        }
    }

    // ---- stage logits to smem; column softmax ----
#pragma unroll
    for (int j = 0; j < 8; j++) {
        *(float2*)&lw[warp][r1][8 * j + base]     = make_float2(d[j][0], d[j][1]);
        *(float2*)&lw[warp][r1 + 8][8 * j + base] = make_float2(d[j][2], d[j][3]);
    }
    __syncwarp();
#pragma unroll
    for (int cc = 0; cc < 2; cc++) {
        const int c = lane + 32 * cc;
        float mx = -3.4e38f;
#pragma unroll
        for (int k = 0; k < 16; k++) mx = fmaxf(mx, lw[warp][k][c]);
        float s = 0.f, o = 0.f;
#pragma unroll
        for (int k = 0; k < 16; k++) {
            const float e = __expf(lw[warp][k][c] - mx);
            s += e;
            o = fmaf(e, mygv[k * GVS + c], o);
        }
        mout[warp][c] = __fdividef(o, s);
    }
    __syncthreads();

    // ---- final GEMM via mma: out = mout @ wo + bo + residual ----
    // A rows 4..15 are structurally zero -> zero fragments, no smem init.
    {
        u32 aH2[16], aL2[16];
#pragma unroll
        for (int m = 0; m < 8; m++) {
            const int kt = m >> 1;
            const int ro = (m & 1) << 1;
            if (r1 < 4) {
                const float2 fA = *(const float2*)&mout[r1][8 * m + base];
                bsplit2(fA.x, fA.y, aH2[kt * 4 + ro], aL2[kt * 4 + ro]);
            } else {
                aH2[kt * 4 + ro] = 0u; aL2[kt * 4 + ro] = 0u;
            }
            aH2[kt * 4 + ro + 1] = 0u; aL2[kt * 4 + ro + 1] = 0u;
        }
        float dd[2][4];
#pragma unroll
        for (int jj = 0; jj < 2; jj++)
#pragma unroll
            for (int i = 0; i < 4; i++) dd[jj][i] = 0.f;
#pragma unroll
        for (int kt = 0; kt < 4; kt++) {
#pragma unroll
            for (int jj = 0; jj < 2; jj++) {
                const int j = 2 * warp + jj;
                const uint2 bh = __ldg(&g_bfrag[10240 + j * 128 + kt * 32 + lane]);
                const uint2 bl = __ldg(&g_bfrag[11264 + j * 128 + kt * 32 + lane]);
                mma16816(dd[jj], &aH2[kt * 4], bh);
                mma16816(dd[jj], &aL2[kt * 4], bh);
                mma16816(dd[jj], &aH2[kt * 4], bl);
            }
        }
        if (r1 < 4) {
            const int n3 = blockIdx.x * 4 + r1;
            if (n3 < N) {
#pragma unroll
                for (int jj = 0; jj < 2; jj++) {
                    const int c = 8 * (2 * warp + jj) + base;
                    const float2 b2 = __ldg((const float2*)(bo + c));
                    const float2 f2 = *(const float2*)(feat + n3 * 64 + c);
                    *(float2*)(out + n3 * 64 + c) =
                        make_float2(dd[jj][0] + b2.x + f2.x,
                                    dd[jj][1] + b2.y + f2.y);
                }
            }
        }
    }
}

// ---------------------------------------------------------------------------
extern "C" void kernel_launch(void* const* d_in, const int* in_sizes, int n_in,
                              void* d_out, int out_size)
{
    const float* points = (const float*)d_in[0];
    const float* feat   = (const float*)d_in[1];
    const int*   nbr    = (const int*)  d_in[2];
    const float* wq     = (const float*)d_in[3];
    const float* bq     = (const float*)d_in[4];
    const float* wk     = (const float*)d_in[5];
    const float* bk     = (const float*)d_in[6];
    const float* wv     = (const float*)d_in[7];
    const float* bv     = (const float*)d_in[8];
    const float* wp     = (const float*)d_in[9];
    const float* bp     = (const float*)d_in[10];
    const float* gp     = (const float*)d_in[11];
    const float* betap  = (const float*)d_in[12];
    const float* wg1    = (const float*)d_in[13];
    const float* bg1    = (const float*)d_in[14];
    const float* gg     = (const float*)d_in[15];
    const float* betag  = (const float*)d_in[16];
    const float* wg2    = (const float*)d_in[17];
    const float* bg2    = (const float*)d_in[18];
    const float* wo     = (const float*)d_in[19];
    const float* bo     = (const float*)d_in[20];
    float* out = (float*)d_out;
    (void)bg2;

    const int N = in_sizes[0] / 3;

    build_kernel<<<49, 256>>>(wg1, wg2, wq, wk, wv, wo, wp, bp);
    qkv_mma_kernel<<<(N + 63) / 64, 128>>>(feat, N, bq, bk, bv);
    pt_mma_kernel<<<(N + 3) / 4, 128>>>(points, feat, nbr, N,
                                        wp, bp, gp, betap,
                                        bg1, gg, betag, bo, out);
}

// round 10
// speedup vs baseline: 2.4212x; 1.0595x over previous
#include <cuda_runtime.h>
#include <cuda_bf16.h>

#define NMAX 50176
#define LN_EPS 1e-5f

__device__ float g_q[NMAX * 64];
__device__ float g_k[NMAX * 64];
__device__ float g_v[NMAX * 64];

// packed B fragments: [weight(6: wg1,wg2,wq,wk,wv,wo)][j(8)][kt(4)][lane(32)]
// entry = {bh0, bh1, bl0, bl1}
__device__ uint4 g_bfragP[6144];
__device__ float g_gram[20];
__device__ float g_pp[384];   // permuted positional params: wx|wy|wz|bp|gp|betap

typedef unsigned long long u64;
typedef unsigned int u32;

__device__ __forceinline__ u32 cvt2bf(float hi, float lo) {
    u32 r;
    asm("cvt.rn.bf16x2.f32 %0, %1, %2;" : "=r"(r) : "f"(hi), "f"(lo));
    return r;
}
// split (x,y) into packed bf16x2 hi and lo parts (x in low half)
__device__ __forceinline__ void bsplit2(float x, float y, u32& hp, u32& lp) {
    hp = cvt2bf(y, x);
    const float hx = __uint_as_float(hp << 16);
    const float hy = __uint_as_float(hp & 0xFFFF0000u);
    lp = cvt2bf(y - hy, x - hx);
}
__device__ __forceinline__ void mma16816(float* d, const u32* a, u32 b0, u32 b1) {
    asm volatile(
        "mma.sync.aligned.m16n8k16.row.col.f32.bf16.bf16.f32 "
        "{%0,%1,%2,%3}, {%4,%5,%6,%7}, {%8,%9}, {%0,%1,%2,%3};"
        : "+f"(d[0]), "+f"(d[1]), "+f"(d[2]), "+f"(d[3])
        : "r"(a[0]), "r"(a[1]), "r"(a[2]), "r"(a[3]), "r"(b0), "r"(b1));
}

// ---------------------------------------------------------------------------
// Init: packed B fragments for 6 weights + permuted pos-params + Gram. 25 CTAs.
// ---------------------------------------------------------------------------
__global__ void build_kernel(const float* __restrict__ wg1,
                             const float* __restrict__ wg2,
                             const float* __restrict__ wq,
                             const float* __restrict__ wk,
                             const float* __restrict__ wv,
                             const float* __restrict__ wo,
                             const float* __restrict__ wp,
                             const float* __restrict__ bp,
                             const float* __restrict__ gp,
                             const float* __restrict__ betap)
{
    const int t = threadIdx.x;
    if (blockIdx.x < 24) {
        const int e = blockIdx.x * 256 + t;
        const int lane = e & 31;
        const int kt   = (e >> 5) & 3;
        const int j    = (e >> 7) & 7;
        const int wi   = e >> 10;
        const float* Wt[6] = { wg1, wg2, wq, wk, wv, wo };
        const float* W = Wt[wi];
        const int n  = 8 * j + (lane >> 2);
        const int k0 = 16 * kt + 2 * (lane & 3);
        u32 h0, l0, h1, l1;
        bsplit2(W[k0 * 64 + n],       W[(k0 + 1) * 64 + n], h0, l0);
        bsplit2(W[(k0 + 8) * 64 + n], W[(k0 + 9) * 64 + n], h1, l1);
        g_bfragP[e] = make_uint4(h0, h1, l0, l1);
    } else {
        if (t < 64) {
            // permuted positional params: p -> true col
            const int p = t;
            const int kt = p >> 4, q = (p >> 2) & 3, i = p & 3;
            const int tc = 16 * kt + ((i < 2) ? (2 * q + i) : (6 + 2 * q + i));
            g_pp[0 * 64 + p] = wp[tc];
            g_pp[1 * 64 + p] = wp[64 + tc];
            g_pp[2 * 64 + p] = wp[128 + tc];
            g_pp[3 * 64 + p] = bp[tc];
            g_pp[4 * 64 + p] = gp[tc];
            g_pp[5 * 64 + p] = betap[tc];
        } else if (t < 84) {
            const int tt = t - 64;
            if (tt < 16) {
                const int a = tt >> 2, b = tt & 3;
                const float* ra = (a < 3) ? (wp + a * 64) : bp;
                const float* rb = (b < 3) ? (wp + b * 64) : bp;
                float s = 0.f;
                for (int c = 0; c < 64; c++) s += ra[c] * rb[c];
                g_gram[tt] = s;
            } else {
                const int a = tt - 16;
                const float* ra = (a < 3) ? (wp + a * 64) : bp;
                float s = 0.f;
                for (int c = 0; c < 64; c++) s += ra[c];
                g_gram[tt] = s;
            }
        }
    }
}

// ---------------------------------------------------------------------------
// Kernel A: q/k/v via mma.sync bf16-split; writes g_q/g_k/g_v in the
// K-PERMUTED layout (p = 16kt + 4q + i  <->  true 16kt + {2q,2q+1,8+2q,9+2q}).
// ---------------------------------------------------------------------------
__global__ __launch_bounds__(128, 4) void qkv_mma_kernel(
    const float* __restrict__ feat, int N,
    const float* __restrict__ bq, const float* __restrict__ bk,
    const float* __restrict__ bv)
{
    const int t = threadIdx.x;
    const int lane = t & 31;
    const int warp = t >> 5;
    const int qd = lane & 3;
    const int base = 2 * qd;
    const int r1 = lane >> 2;

    const int row0 = (blockIdx.x * 4 + warp) * 16;
    const int rowA = row0 + r1;
    const int rowB = row0 + r1 + 8;
    const int rowAc = (rowA < N) ? rowA : N - 1;
    const int rowBc = (rowB < N) ? rowB : N - 1;

    u32 aHi[16], aLo[16];
#pragma unroll
    for (int m = 0; m < 8; m++) {
        const int c = 8 * m + base;
        const float2 fA = *(const float2*)(feat + rowAc * 64 + c);
        const float2 fB = *(const float2*)(feat + rowBc * 64 + c);
        const int kt = m >> 1;
        const int ro = (m & 1) << 1;
        bsplit2(fA.x, fA.y, aHi[kt * 4 + ro],     aLo[kt * 4 + ro]);
        bsplit2(fB.x, fB.y, aHi[kt * 4 + ro + 1], aLo[kt * 4 + ro + 1]);
    }

    const float* Bs[3] = { bq, bk, bv };
    float* Gs[3] = { g_q, g_k, g_v };
#pragma unroll 1
    for (int wi = 0; wi < 3; wi++) {
        const uint4* fr = g_bfragP + (2 + wi) * 1024;
        float d[8][4];
#pragma unroll
        for (int j = 0; j < 8; j++)
#pragma unroll
            for (int i = 0; i < 4; i++) d[j][i] = 0.f;
#pragma unroll
        for (int kt = 0; kt < 4; kt++) {
#pragma unroll
            for (int j = 0; j < 8; j++) {
                const uint4 e = __ldg(&fr[j * 128 + kt * 32 + lane]);
                mma16816(d[j], &aHi[kt * 4], e.x, e.y);
                mma16816(d[j], &aLo[kt * 4], e.x, e.y);
                mma16816(d[j], &aHi[kt * 4], e.z, e.w);
            }
        }
        float* G = Gs[wi];
        const float* B = Bs[wi];
#pragma unroll
        for (int j = 0; j < 8; j++) {
            const float2 b2 = __ldg((const float2*)(B + 8 * j + base));
            const int P = 16 * (j >> 1) + 4 * qd + ((j & 1) << 1);  // permuted
            if (rowA < N)
                *(float2*)(G + rowA * 64 + P) =
                    make_float2(d[j][0] + b2.x, d[j][1] + b2.y);
            if (rowB < N)
                *(float2*)(G + rowB * 64 + P) =
                    make_float2(d[j][2] + b2.x, d[j][3] + b2.y);
        }
    }
}

// ---------------------------------------------------------------------------
// Kernel B: one warp per point; float4 gathers from permuted q/k/v;
// packed B-frag loads; smem softmax; mma final GEMM. 6 CTA/SM.
// ---------------------------------------------------------------------------
#define GVS 66
#define LWS 66

__global__ __launch_bounds__(128, 6) void pt_mma_kernel(
    const float* __restrict__ points, const float* __restrict__ feat,
    const int* __restrict__ nbr, int N,
    const float* __restrict__ bg1, const float* __restrict__ gg,
    const float* __restrict__ betag,
    const float* __restrict__ bo,
    float* __restrict__ out)
{
    __shared__ float gvs[4 * 16 * GVS];   // 16896 B
    __shared__ float lw[4][16][LWS];      // 16896 B
    __shared__ float mout[4][LWS];        // 1056 B

    const int t = threadIdx.x;
    const int lane = t & 31;
    const int warp = t >> 5;

    int n = blockIdx.x * 4 + warp;
    if (n >= N) n = N - 1;

    const int qd = lane & 3;
    const int base = 2 * qd;
    const int r1 = lane >> 2;
    float* mygv = gvs + warp * 16 * GVS;

    float M[20];
#pragma unroll
    for (int i = 0; i < 20; i++) M[i] = __ldg(&g_gram[i]);

    const int id1 = __ldg(&nbr[n * 16 + r1]);
    const int id2 = __ldg(&nbr[n * 16 + r1 + 8]);
    const float px = __ldg(&points[n * 3 + 0]);
    const float py = __ldg(&points[n * 3 + 1]);
    const float pz = __ldg(&points[n * 3 + 2]);
    const float rx1 = __ldg(&points[id1 * 3 + 0]) - px;
    const float ry1 = __ldg(&points[id1 * 3 + 1]) - py;
    const float rz1 = __ldg(&points[id1 * 3 + 2]) - pz;
    const float rx2 = __ldg(&points[id2 * 3 + 0]) - px;
    const float ry2 = __ldg(&points[id2 * 3 + 1]) - py;
    const float rz2 = __ldg(&points[id2 * 3 + 2]) - pz;

    float mean1, inv1, mean2, inv2;
    {
        const float s1 = fmaf(rx1, M[16], fmaf(ry1, M[17], fmaf(rz1, M[18], M[19])));
        const float tx = fmaf(rx1, M[0],  fmaf(ry1, M[1],  fmaf(rz1, M[2],  M[3])));
        const float ty = fmaf(rx1, M[4],  fmaf(ry1, M[5],  fmaf(rz1, M[6],  M[7])));
        const float tz = fmaf(rx1, M[8],  fmaf(ry1, M[9],  fmaf(rz1, M[10], M[11])));
        const float tw = fmaf(rx1, M[12], fmaf(ry1, M[13], fmaf(rz1, M[14], M[15])));
        const float s2 = fmaf(rx1, tx, fmaf(ry1, ty, fmaf(rz1, tz, tw)));
        mean1 = s1 * 0.015625f;
        inv1 = rsqrtf(s2 * 0.015625f - mean1 * mean1 + LN_EPS);
    }
    {
        const float s1 = fmaf(rx2, M[16], fmaf(ry2, M[17], fmaf(rz2, M[18], M[19])));
        const float tx = fmaf(rx2, M[0],  fmaf(ry2, M[1],  fmaf(rz2, M[2],  M[3])));
        const float ty = fmaf(rx2, M[4],  fmaf(ry2, M[5],  fmaf(rz2, M[6],  M[7])));
        const float tz = fmaf(rx2, M[8],  fmaf(ry2, M[9],  fmaf(rz2, M[10], M[11])));
        const float tw = fmaf(rx2, M[12], fmaf(ry2, M[13], fmaf(rz2, M[14], M[15])));
        const float s2 = fmaf(rx2, tx, fmaf(ry2, ty, fmaf(rz2, tz, tw)));
        mean2 = s1 * 0.015625f;
        inv2 = rsqrtf(s2 * 0.015625f - mean2 * mean2 + LN_EPS);
    }

    // ---- gather (float4, permuted) + positional LN/relu -> A frags; gv -> SMEM
    u32 aHi[16], aLo[16];
#pragma unroll
    for (int kt = 0; kt < 4; kt++) {
        const int pc = 16 * kt + 4 * qd;   // permuted base column
        const float4 q4  = *(const float4*)(g_q + n * 64 + pc);
        const float4 k1v = *(const float4*)(g_k + id1 * 64 + pc);
        const float4 k2v = *(const float4*)(g_k + id2 * 64 + pc);
        const float4 v1v = *(const float4*)(g_v + id1 * 64 + pc);
        const float4 v2v = *(const float4*)(g_v + id2 * 64 + pc);
        const float4 wxv = __ldg((const float4*)(g_pp + 0 * 64 + pc));
        const float4 wyv = __ldg((const float4*)(g_pp + 1 * 64 + pc));
        const float4 wzv = __ldg((const float4*)(g_pp + 2 * 64 + pc));
        const float4 bpv = __ldg((const float4*)(g_pp + 3 * 64 + pc));
        const float4 gpv = __ldg((const float4*)(g_pp + 4 * 64 + pc));
        const float4 bev = __ldg((const float4*)(g_pp + 5 * 64 + pc));

        float vA[4], vB[4];
        {
            const float* wx = &wxv.x; const float* wy = &wyv.x;
            const float* wz = &wzv.x; const float* bb = &bpv.x;
            const float* gg2 = &gpv.x; const float* be = &bev.x;
#pragma unroll
            for (int i = 0; i < 4; i++) {
                const float pA = fmaf(rx1, wx[i], fmaf(ry1, wy[i],
                                 fmaf(rz1, wz[i], bb[i])));
                const float pB = fmaf(rx2, wx[i], fmaf(ry2, wy[i],
                                 fmaf(rz2, wz[i], bb[i])));
                vA[i] = fmaxf(fmaf((pA - mean1) * inv1, gg2[i], be[i]), 0.f);
                vB[i] = fmaxf(fmaf((pB - mean2) * inv2, gg2[i], be[i]), 0.f);
            }
        }

        bsplit2(q4.x - k1v.x + vA[0], q4.y - k1v.y + vA[1],
                aHi[kt * 4 + 0], aLo[kt * 4 + 0]);
        bsplit2(q4.x - k2v.x + vB[0], q4.y - k2v.y + vB[1],
                aHi[kt * 4 + 1], aLo[kt * 4 + 1]);
        bsplit2(q4.z - k1v.z + vA[2], q4.w - k1v.w + vA[3],
                aHi[kt * 4 + 2], aLo[kt * 4 + 2]);
        bsplit2(q4.z - k2v.z + vB[2], q4.w - k2v.w + vB[3],
                aHi[kt * 4 + 3], aLo[kt * 4 + 3]);

        // gv+p stored at TRUE columns
        *(float2*)(mygv + r1 * GVS + 16 * kt + base) =
            make_float2(v1v.x + vA[0], v1v.y + vA[1]);
        *(float2*)(mygv + (r1 + 8) * GVS + 16 * kt + base) =
            make_float2(v2v.x + vB[0], v2v.y + vB[1]);
        *(float2*)(mygv + r1 * GVS + 16 * kt + 8 + base) =
            make_float2(v1v.z + vA[2], v1v.w + vA[3]);
        *(float2*)(mygv + (r1 + 8) * GVS + 16 * kt + 8 + base) =
            make_float2(v2v.z + vB[2], v2v.w + vB[3]);
    }

    // ---- GEMM1: d = attn @ wg1 ----
    float d[8][4];
#pragma unroll
    for (int j = 0; j < 8; j++)
#pragma unroll
        for (int i = 0; i < 4; i++) d[j][i] = 0.f;
#pragma unroll
    for (int kt = 0; kt < 4; kt++) {
#pragma unroll
        for (int j = 0; j < 8; j++) {
            const uint4 e = __ldg(&g_bfragP[j * 128 + kt * 32 + lane]);
            mma16816(d[j], &aHi[kt * 4], e.x, e.y);
            mma16816(d[j], &aLo[kt * 4], e.x, e.y);
            mma16816(d[j], &aHi[kt * 4], e.z, e.w);
        }
    }

    // ---- LN + relu over rows (4-lane groups) ----
    {
        float s1a = 0.f, s2a = 0.f, s1b = 0.f, s2b = 0.f;
#pragma unroll
        for (int j = 0; j < 8; j++) {
            const float2 bg = __ldg((const float2*)(bg1 + 8 * j + base));
            d[j][0] += bg.x; d[j][1] += bg.y;
            d[j][2] += bg.x; d[j][3] += bg.y;
            s1a += d[j][0] + d[j][1];
            s2a += d[j][0] * d[j][0] + d[j][1] * d[j][1];
            s1b += d[j][2] + d[j][3];
            s2b += d[j][2] * d[j][2] + d[j][3] * d[j][3];
        }
#pragma unroll
        for (int off = 1; off <= 2; off <<= 1) {
            s1a += __shfl_xor_sync(0xffffffffu, s1a, off);
            s2a += __shfl_xor_sync(0xffffffffu, s2a, off);
            s1b += __shfl_xor_sync(0xffffffffu, s1b, off);
            s2b += __shfl_xor_sync(0xffffffffu, s2b, off);
        }
        const float m1 = s1a * 0.015625f;
        const float i1 = rsqrtf(s2a * 0.015625f - m1 * m1 + LN_EPS);
        const float m2 = s1b * 0.015625f;
        const float i2 = rsqrtf(s2b * 0.015625f - m2 * m2 + LN_EPS);
#pragma unroll
        for (int j = 0; j < 8; j++) {
            const int c = 8 * j + base;
            const float2 gA = __ldg((const float2*)(gg + c));
            const float2 bA = __ldg((const float2*)(betag + c));
            d[j][0] = fmaxf(fmaf((d[j][0] - m1) * i1, gA.x, bA.x), 0.f);
            d[j][1] = fmaxf(fmaf((d[j][1] - m1) * i1, gA.y, bA.y), 0.f);
            d[j][2] = fmaxf(fmaf((d[j][2] - m2) * i2, gA.x, bA.x), 0.f);
            d[j][3] = fmaxf(fmaf((d[j][3] - m2) * i2, gA.y, bA.y), 0.f);
        }
    }

    // ---- repack h into A fragments ----
#pragma unroll
    for (int kt = 0; kt < 4; kt++) {
        bsplit2(d[2 * kt][0],     d[2 * kt][1],     aHi[kt * 4 + 0], aLo[kt * 4 + 0]);
        bsplit2(d[2 * kt][2],     d[2 * kt][3],     aHi[kt * 4 + 1], aLo[kt * 4 + 1]);
        bsplit2(d[2 * kt + 1][0], d[2 * kt + 1][1], aHi[kt * 4 + 2], aLo[kt * 4 + 2]);
        bsplit2(d[2 * kt + 1][2], d[2 * kt + 1][3], aHi[kt * 4 + 3], aLo[kt * 4 + 3]);
    }

    // ---- GEMM2: logits = h @ wg2 (bg2 cancels in softmax) ----
#pragma unroll
    for (int j = 0; j < 8; j++)
#pragma unroll
        for (int i = 0; i < 4; i++) d[j][i] = 0.f;
#pragma unroll
    for (int kt = 0; kt < 4; kt++) {
#pragma unroll
        for (int j = 0; j < 8; j++) {
            const uint4 e = __ldg(&g_bfragP[1024 + j * 128 + kt * 32 + lane]);
            mma16816(d[j], &aHi[kt * 4], e.x, e.y);
            mma16816(d[j], &aLo[kt * 4], e.x, e.y);
            mma16816(d[j], &aHi[kt * 4], e.z, e.w);
        }
    }

    // ---- stage logits to smem; column softmax ----
#pragma unroll
    for (int j = 0; j < 8; j++) {
        *(float2*)&lw[warp][r1][8 * j + base]     = make_float2(d[j][0], d[j][1]);
        *(float2*)&lw[warp][r1 + 8][8 * j + base] = make_float2(d[j][2], d[j][3]);
    }
    __syncwarp();
#pragma unroll
    for (int cc = 0; cc < 2; cc++) {
        const int c = lane + 32 * cc;
        float mx = -3.4e38f;
#pragma unroll
        for (int k = 0; k < 16; k++) mx = fmaxf(mx, lw[warp][k][c]);
        float s = 0.f, o = 0.f;
#pragma unroll
        for (int k = 0; k < 16; k++) {
            const float e = __expf(lw[warp][k][c] - mx);
            s += e;
            o = fmaf(e, mygv[k * GVS + c], o);
        }
        mout[warp][c] = __fdividef(o, s);
    }
    __syncthreads();

    // ---- final GEMM via mma: out = mout @ wo + bo + residual ----
    {
        u32 aH2[16], aL2[16];
#pragma unroll
        for (int m = 0; m < 8; m++) {
            const int kt = m >> 1;
            const int ro = (m & 1) << 1;
            if (r1 < 4) {
                const float2 fA = *(const float2*)&mout[r1][8 * m + base];
                bsplit2(fA.x, fA.y, aH2[kt * 4 + ro], aL2[kt * 4 + ro]);
            } else {
                aH2[kt * 4 + ro] = 0u; aL2[kt * 4 + ro] = 0u;
            }
            aH2[kt * 4 + ro + 1] = 0u; aL2[kt * 4 + ro + 1] = 0u;
        }
        float dd[2][4];
#pragma unroll
        for (int jj = 0; jj < 2; jj++)
#pragma unroll
            for (int i = 0; i < 4; i++) dd[jj][i] = 0.f;
#pragma unroll
        for (int kt = 0; kt < 4; kt++) {
#pragma unroll
            for (int jj = 0; jj < 2; jj++) {
                const int j = 2 * warp + jj;
                const uint4 e = __ldg(&g_bfragP[5120 + j * 128 + kt * 32 + lane]);
                mma16816(dd[jj], &aH2[kt * 4], e.x, e.y);
                mma16816(dd[jj], &aL2[kt * 4], e.x, e.y);
                mma16816(dd[jj], &aH2[kt * 4], e.z, e.w);
            }
        }
        if (r1 < 4) {
            const int n3 = blockIdx.x * 4 + r1;
            if (n3 < N) {
#pragma unroll
                for (int jj = 0; jj < 2; jj++) {
                    const int c = 8 * (2 * warp + jj) + base;
                    const float2 b2 = __ldg((const float2*)(bo + c));
                    const float2 f2 = *(const float2*)(feat + n3 * 64 + c);
                    *(float2*)(out + n3 * 64 + c) =
                        make_float2(dd[jj][0] + b2.x + f2.x,
                                    dd[jj][1] + b2.y + f2.y);
                }
            }
        }
    }
}

// ---------------------------------------------------------------------------
extern "C" void kernel_launch(void* const* d_in, const int* in_sizes, int n_in,
                              void* d_out, int out_size)
{
    const float* points = (const float*)d_in[0];
    const float* feat   = (const float*)d_in[1];
    const int*   nbr    = (const int*)  d_in[2];
    const float* wq     = (const float*)d_in[3];
    const float* bq     = (const float*)d_in[4];
    const float* wk     = (const float*)d_in[5];
    const float* bk     = (const float*)d_in[6];
    const float* wv     = (const float*)d_in[7];
    const float* bv     = (const float*)d_in[8];
    const float* wp     = (const float*)d_in[9];
    const float* bp     = (const float*)d_in[10];
    const float* gp     = (const float*)d_in[11];
    const float* betap  = (const float*)d_in[12];
    const float* wg1    = (const float*)d_in[13];
    const float* bg1    = (const float*)d_in[14];
    const float* gg     = (const float*)d_in[15];
    const float* betag  = (const float*)d_in[16];
    const float* wg2    = (const float*)d_in[17];
    const float* bg2    = (const float*)d_in[18];
    const float* wo     = (const float*)d_in[19];
    const float* bo     = (const float*)d_in[20];
    float* out = (float*)d_out;
    (void)bg2;

    const int N = in_sizes[0] / 3;

    build_kernel<<<25, 256>>>(wg1, wg2, wq, wk, wv, wo, wp, bp, gp, betap);
    qkv_mma_kernel<<<(N + 63) / 64, 128>>>(feat, N, bq, bk, bv);
    pt_mma_kernel<<<(N + 3) / 4, 128>>>(points, feat, nbr, N,
                                        bg1, gg, betag, bo, out);
}